// round 1
// baseline (speedup 1.0000x reference)
#include <cuda_runtime.h>
#include <cuda_bf16.h>
#include <cstddef>

#define BnW   2048
#define NW    144
#define DIM   256
#define NH    8
#define HD    32
#define NTOK  (BnW * NW)            /* 294912 */
#define QKVN  (3 * DIM)             /* 768 */

// ---------------- scratch (device globals: allocation-free rule) -------------
__device__ float g_qkv[(size_t)NTOK * QKVN];   // [token][768]  q|k|v blocks
__device__ float g_att[(size_t)NTOK * DIM];    // attention output, x-layout
__device__ float g_bias[NH * NW * NW];         // [h][n][m] combined RPB

// ---------------- bias build: bias[h][n][m] = rpb[rel[n][m]][h] --------------
__global__ __launch_bounds__(256) void build_bias_kernel(
    const float* __restrict__ rpb, const int* __restrict__ rel) {
    int idx = blockIdx.x * 256 + threadIdx.x;   // over NW*NW = 20736
    if (idx < NW * NW) {
        int r = rel[idx];
#pragma unroll
        for (int h = 0; h < NH; h++)
            g_bias[h * (NW * NW) + idx] = rpb[r * NH + h];
    }
}

// ---------------- tiled SGEMM: C[M,N] = A[M,K] @ B[K,N] + bias[N] ------------
// BM=BN=128, BK=8, 256 threads, 8x8 per thread. M%128==0, N%128==0, K%8==0.
__global__ __launch_bounds__(256) void sgemm_bias_kernel(
    const float* __restrict__ A, const float* __restrict__ B,
    const float* __restrict__ bias, float* __restrict__ C,
    int N, int K) {
    __shared__ float As[8][128];
    __shared__ float Bs[8][128];

    const int tid = threadIdx.x;
    const int tx = tid & 15;       // 0..15 -> N sub-tile
    const int ty = tid >> 4;       // 0..15 -> M sub-tile
    const size_t aBase = (size_t)blockIdx.y * 128 * K;
    const int bCol = blockIdx.x * 128;

    const int arow = tid >> 1;               // 0..127
    const int aseg = (tid & 1) * 4;          // 0 or 4
    const int brow = tid >> 5;               // 0..7
    const int bcol = (tid & 31) * 4;         // 0..124

    float acc[8][8];
#pragma unroll
    for (int i = 0; i < 8; i++)
#pragma unroll
        for (int j = 0; j < 8; j++) acc[i][j] = 0.f;

    for (int k0 = 0; k0 < K; k0 += 8) {
        float4 a4 = *reinterpret_cast<const float4*>(
            A + aBase + (size_t)arow * K + k0 + aseg);
        As[aseg + 0][arow] = a4.x;
        As[aseg + 1][arow] = a4.y;
        As[aseg + 2][arow] = a4.z;
        As[aseg + 3][arow] = a4.w;
        float4 b4 = *reinterpret_cast<const float4*>(
            B + (size_t)(k0 + brow) * N + bCol + bcol);
        *reinterpret_cast<float4*>(&Bs[brow][bcol]) = b4;
        __syncthreads();

#pragma unroll
        for (int k = 0; k < 8; k++) {
            float4 ra0 = *reinterpret_cast<const float4*>(&As[k][ty * 8]);
            float4 ra1 = *reinterpret_cast<const float4*>(&As[k][ty * 8 + 4]);
            float4 rb0 = *reinterpret_cast<const float4*>(&Bs[k][tx * 8]);
            float4 rb1 = *reinterpret_cast<const float4*>(&Bs[k][tx * 8 + 4]);
            float ra[8] = {ra0.x, ra0.y, ra0.z, ra0.w, ra1.x, ra1.y, ra1.z, ra1.w};
            float rb[8] = {rb0.x, rb0.y, rb0.z, rb0.w, rb1.x, rb1.y, rb1.z, rb1.w};
#pragma unroll
            for (int i = 0; i < 8; i++)
#pragma unroll
                for (int j = 0; j < 8; j++)
                    acc[i][j] = fmaf(ra[i], rb[j], acc[i][j]);
        }
        __syncthreads();
    }

    const size_t row0 = (size_t)blockIdx.y * 128 + ty * 8;
    const int col0 = bCol + tx * 8;
#pragma unroll
    for (int i = 0; i < 8; i++) {
        size_t cbase = (row0 + i) * (size_t)N + col0;
#pragma unroll
        for (int j = 0; j < 8; j++)
            C[cbase + j] = acc[i][j] + bias[col0 + j];
    }
}

// ---------------- attention: one block per (window, head) --------------------
// smem: Q[144][33] K[144][33] V[144][34] S[144][144] invs[144]
#define QP 33
#define VP 34
#define SMEM_FLOATS (NW * QP * 2 + NW * VP + NW * NW + NW)
#define SMEM_BYTES  (SMEM_FLOATS * 4)

__global__ __launch_bounds__(256) void attn_kernel() {
    extern __shared__ float sm[];
    float* Qs = sm;                       // 144*33
    float* Ks = Qs + NW * QP;             // 144*33
    float* Vs = Ks + NW * QP;             // 144*34
    float* Ss = Vs + NW * VP;             // 144*144
    float* invs = Ss + NW * NW;           // 144

    const int h = blockIdx.x;
    const int b = blockIdx.y;
    const int tid = threadIdx.x;
    const float scale = 0.17677669529663687f;   // 32^-0.5
    const size_t rowBase = (size_t)b * NW;

    // stage bias (coalesced) into S
    {
        const float* bh = g_bias + h * (NW * NW);
        for (int idx = tid; idx < NW * NW; idx += 256)
            Ss[idx] = bh[idx];
    }
    // stage Q (scaled), K, V
    for (int idx = tid; idx < NW * HD; idx += 256) {
        int n = idx >> 5, d = idx & 31;
        size_t g = (rowBase + n) * QKVN + h * HD + d;
        Qs[n * QP + d] = g_qkv[g] * scale;
        Ks[n * QP + d] = g_qkv[g + DIM];
        Vs[n * VP + d] = g_qkv[g + 2 * DIM];
    }
    __syncthreads();

    const int tx = tid & 15;    // 0..15
    const int ty = tid >> 4;    // 0..15

    // S += Q @ K^T   (9x9 per thread over 144x144)
    {
        float acc[9][9];
#pragma unroll
        for (int i = 0; i < 9; i++)
#pragma unroll
            for (int j = 0; j < 9; j++) acc[i][j] = 0.f;
#pragma unroll
        for (int k = 0; k < HD; k++) {
            float ra[9], rb[9];
#pragma unroll
            for (int i = 0; i < 9; i++) ra[i] = Qs[(ty * 9 + i) * QP + k];
#pragma unroll
            for (int j = 0; j < 9; j++) rb[j] = Ks[(tx * 9 + j) * QP + k];
#pragma unroll
            for (int i = 0; i < 9; i++)
#pragma unroll
                for (int j = 0; j < 9; j++)
                    acc[i][j] = fmaf(ra[i], rb[j], acc[i][j]);
        }
#pragma unroll
        for (int i = 0; i < 9; i++) {
            int n = ty * 9 + i;
#pragma unroll
            for (int j = 0; j < 9; j++) {
                int m = tx * 9 + j;
                Ss[n * NW + m] += acc[i][j];
            }
        }
    }
    __syncthreads();

    // softmax per row (warp per row, 18 rows per warp)
    {
        const int lane = tid & 31, w = tid >> 5;
        for (int r = w; r < NW; r += 8) {
            float mx = -1e30f;
            for (int m = lane; m < NW; m += 32) mx = fmaxf(mx, Ss[r * NW + m]);
#pragma unroll
            for (int o = 16; o > 0; o >>= 1)
                mx = fmaxf(mx, __shfl_xor_sync(0xffffffff, mx, o));
            float s = 0.f;
            for (int m = lane; m < NW; m += 32) {
                float e = __expf(Ss[r * NW + m] - mx);
                Ss[r * NW + m] = e;
                s += e;
            }
#pragma unroll
            for (int o = 16; o > 0; o >>= 1)
                s += __shfl_xor_sync(0xffffffff, s, o);
            if (lane == 0) invs[r] = 1.0f / s;
        }
    }
    __syncthreads();

    // O = (P @ V) * inv_sum   (9 rows x 2 cols per thread)
    {
        float a0[9], a1[9];
#pragma unroll
        for (int i = 0; i < 9; i++) { a0[i] = 0.f; a1[i] = 0.f; }
#pragma unroll 4
        for (int m = 0; m < NW; m++) {
            float2 v = *reinterpret_cast<const float2*>(&Vs[m * VP + tx * 2]);
#pragma unroll
            for (int i = 0; i < 9; i++) {
                float p = Ss[(ty * 9 + i) * NW + m];
                a0[i] = fmaf(p, v.x, a0[i]);
                a1[i] = fmaf(p, v.y, a1[i]);
            }
        }
#pragma unroll
        for (int i = 0; i < 9; i++) {
            int n = ty * 9 + i;
            float iv = invs[n];
            float2 o2 = make_float2(a0[i] * iv, a1[i] * iv);
            *reinterpret_cast<float2*>(
                &g_att[(rowBase + n) * DIM + h * HD + tx * 2]) = o2;
        }
    }
}

// ---------------- launch ------------------------------------------------------
extern "C" void kernel_launch(void* const* d_in, const int* in_sizes, int n_in,
                              void* d_out, int out_size) {
    const float* x      = (const float*)d_in[0];
    const float* qkv_w  = (const float*)d_in[1];
    const float* qkv_b  = (const float*)d_in[2];
    const float* proj_w = (const float*)d_in[3];
    const float* proj_b = (const float*)d_in[4];
    const float* rpb    = (const float*)d_in[5];
    const int*   rel    = (const int*)d_in[6];
    float* out = (float*)d_out;

    float* qkvbuf = nullptr;
    float* attbuf = nullptr;
    cudaGetSymbolAddress((void**)&qkvbuf, g_qkv);
    cudaGetSymbolAddress((void**)&attbuf, g_att);

    static bool attr_done = false;
    if (!attr_done) {
        cudaFuncSetAttribute(attn_kernel,
                             cudaFuncAttributeMaxDynamicSharedMemorySize,
                             SMEM_BYTES);
        attr_done = true;
    }

    // 1. bias table
    build_bias_kernel<<<(NW * NW + 255) / 256, 256>>>(rpb, rel);

    // 2. QKV GEMM: [294912,256] @ [256,768]
    sgemm_bias_kernel<<<dim3(QKVN / 128, NTOK / 128), 256>>>(
        x, qkv_w, qkv_b, qkvbuf, QKVN, DIM);

    // 3. attention per (head, window)
    attn_kernel<<<dim3(NH, BnW), 256, SMEM_BYTES>>>();

    // 4. proj GEMM: [294912,256] @ [256,256] -> out
    sgemm_bias_kernel<<<dim3(DIM / 128, NTOK / 128), 256>>>(
        attbuf, proj_w, proj_b, out, DIM, DIM);
}

// round 3
// speedup vs baseline: 1.3938x; 1.3938x over previous
#include <cuda_runtime.h>
#include <cuda_bf16.h>
#include <cstdint>
#include <cstddef>

#define BnW   2048
#define NW    144
#define DIM   256
#define NH    8
#define HD    32
#define NTOK  (BnW * NW)            /* 294912 */
#define QKVN  (3 * DIM)             /* 768 */
#define KEXT  768                   /* split-bf16 extended K */

// ---------------- scratch (device globals: allocation-free rule) -------------
__device__ float         g_qkv[(size_t)NTOK * QKVN];     // fp32 q|k|v
__device__ __nv_bfloat16 g_ax[(size_t)NTOK * KEXT];      // x split-ext [Ah|Al|Ah]
__device__ __nv_bfloat16 g_attx[(size_t)NTOK * KEXT];    // attn out split-ext
__device__ __nv_bfloat16 g_bq[(size_t)QKVN * KEXT];      // qkv_w ext  [Bh|Bh|Bl]
__device__ __nv_bfloat16 g_bp[(size_t)DIM * KEXT];       // proj_w ext
__device__ float         g_bias[NH * NW * NW];           // [h][n][m] RPB

// ======================= baseline-PTX tensor-core helpers ====================
__device__ __forceinline__ uint32_t smem_u32(const void* p) {
    uint32_t a;
    asm("{ .reg .u64 t; cvta.to.shared.u64 t, %1; cvt.u32.u64 %0, t; }"
        : "=r"(a) : "l"(p));
    return a;
}
#define LDMX4(r0, r1, r2, r3, addr) \
    asm volatile("ldmatrix.sync.aligned.m8n8.x4.shared.b16 {%0,%1,%2,%3}, [%4];" \
                 : "=r"(r0), "=r"(r1), "=r"(r2), "=r"(r3) : "r"(addr))
#define MMA16816(d, a, b0, b1) \
    asm volatile("mma.sync.aligned.m16n8k16.row.col.f32.bf16.bf16.f32 " \
                 "{%0,%1,%2,%3}, {%4,%5,%6,%7}, {%8,%9}, {%0,%1,%2,%3};" \
                 : "+f"((d)[0]), "+f"((d)[1]), "+f"((d)[2]), "+f"((d)[3]) \
                 : "r"((a)[0]), "r"((a)[1]), "r"((a)[2]), "r"((a)[3]), \
                   "r"(b0), "r"(b1))
#define CPASYNC16(s, g) \
    asm volatile("cp.async.cg.shared.global [%0], [%1], 16;" :: "r"(s), "l"(g))
#define CP_COMMIT() asm volatile("cp.async.commit_group;" ::: "memory")
#define CP_WAIT1()  asm volatile("cp.async.wait_group 1;" ::: "memory")
#define CP_WAIT0()  asm volatile("cp.async.wait_group 0;" ::: "memory")

// ======================= split-bf16 conversion kernels =======================
__device__ __forceinline__ void bf_split(float f, unsigned short& h, unsigned short& l) {
    __nv_bfloat16 hb = __float2bfloat16(f);
    __nv_bfloat16 lb = __float2bfloat16(f - __bfloat162float(hb));
    h = __bfloat16_as_ushort(hb);
    l = __bfloat16_as_ushort(lb);
}

// x [NTOK,256] fp32 -> g_ax [NTOK,768] = [Ah|Al|Ah]
__global__ __launch_bounds__(256) void conv_x_kernel(const float* __restrict__ x) {
    size_t i = (size_t)blockIdx.x * 256 + threadIdx.x;   // over NTOK*64
    size_t row = i >> 6;
    int c4 = (int)(i & 63) * 4;
    float4 v = *reinterpret_cast<const float4*>(x + row * DIM + c4);
    ushort4 hv, lv;
    bf_split(v.x, hv.x, lv.x); bf_split(v.y, hv.y, lv.y);
    bf_split(v.z, hv.z, lv.z); bf_split(v.w, hv.w, lv.w);
    __nv_bfloat16* base = g_ax + row * KEXT;
    *reinterpret_cast<ushort4*>(base + c4)       = hv;
    *reinterpret_cast<ushort4*>(base + 256 + c4) = lv;
    *reinterpret_cast<ushort4*>(base + 512 + c4) = hv;
}

// w [256,N] fp32 -> Bext [N,768] = [Bh|Bh|Bl]
__global__ __launch_bounds__(256) void conv_w_kernel(const float* __restrict__ w,
                                                     __nv_bfloat16* __restrict__ Bext,
                                                     int N) {
    int i = blockIdx.x * 256 + threadIdx.x;   // over N*256
    if (i >= N * 256) return;
    int n = i >> 8, k = i & 255;
    unsigned short h, l;
    bf_split(w[k * N + n], h, l);
    Bext[(size_t)n * KEXT + k]       = __ushort_as_bfloat16(h);
    Bext[(size_t)n * KEXT + 256 + k] = __ushort_as_bfloat16(h);
    Bext[(size_t)n * KEXT + 512 + k] = __ushort_as_bfloat16(l);
}

// ---------------- bias build: bias[h][n][m] = rpb[rel[n][m]][h] --------------
__global__ __launch_bounds__(256) void build_bias_kernel(
    const float* __restrict__ rpb, const int* __restrict__ rel) {
    int idx = blockIdx.x * 256 + threadIdx.x;
    if (idx < NW * NW) {
        int r = rel[idx];
#pragma unroll
        for (int h = 0; h < NH; h++)
            g_bias[h * (NW * NW) + idx] = rpb[r * NH + h];
    }
}

// ======================= mma.sync GEMM: C = Aext @ Bext^T + bias =============
// A [M,KEXT] bf16 row-major, B [Ntot,KEXT] bf16 row-major (acts as B^T).
// tile 128x128x32, 256 threads = 8 warps (2M x 4N), warp tile 64x32.
#define NCHUNK 24                       /* 768 / 32 */
#define SPITCH 80                       /* bytes per 32-bf16 row, +16B pad */
#define STAGE_BYTES (128 * SPITCH)      /* 10240 per matrix per stage */

__global__ __launch_bounds__(256) void gemm_mma_kernel(
    const __nv_bfloat16* __restrict__ Aext,
    const __nv_bfloat16* __restrict__ Bext,
    const float* __restrict__ bias,
    float* __restrict__ C, int Ntot) {
    __shared__ char sA[2 * STAGE_BYTES];
    __shared__ char sB[2 * STAGE_BYTES];

    const int tid = threadIdx.x;
    const int w = tid >> 5, l = tid & 31;
    const int wm = w & 1, wn = w >> 1;            // 2 x 4 warp grid
    const int tileN = blockIdx.x, tileM = blockIdx.y;

    const uint32_t sAb = smem_u32(sA);
    const uint32_t sBb = smem_u32(sB);

    const char* Ab = reinterpret_cast<const char*>(Aext) +
                     (size_t)tileM * 128 * (KEXT * 2);
    const char* Bb = reinterpret_cast<const char*>(Bext) +
                     (size_t)tileN * 128 * (KEXT * 2);

    // per-thread load slots: rows (tid>>2, tid>>2+64), 16B seg (tid&3)
    const int lrow = tid >> 2;
    const int lseg = (tid & 3) * 16;

    float acc[4][4][4];
#pragma unroll
    for (int mf = 0; mf < 4; mf++)
#pragma unroll
        for (int nf = 0; nf < 4; nf++)
#pragma unroll
            for (int r = 0; r < 4; r++) acc[mf][nf][r] = 0.f;

    // prologue: stage 0
    {
        const size_t go = (size_t)lrow * (KEXT * 2) + lseg;
        const size_t go2 = (size_t)(lrow + 64) * (KEXT * 2) + lseg;
        CPASYNC16(sAb + lrow * SPITCH + lseg, Ab + go);
        CPASYNC16(sAb + (lrow + 64) * SPITCH + lseg, Ab + go2);
        CPASYNC16(sBb + lrow * SPITCH + lseg, Bb + go);
        CPASYNC16(sBb + (lrow + 64) * SPITCH + lseg, Bb + go2);
        CP_COMMIT();
    }

    // ldmatrix source addresses (fixed per thread, + stage/k offsets)
    const uint32_t aRowOff = (uint32_t)(wm * 64 + (l & 15)) * SPITCH + (l >> 4) * 16;
    const uint32_t bRowOff = (uint32_t)(wn * 32 + ((l >> 4) * 8 + (l & 7))) * SPITCH +
                             ((l >> 3) & 1) * 16;

    for (int c = 0; c < NCHUNK; c++) {
        if (c + 1 < NCHUNK) {
            const int nb = (c + 1) & 1;
            const int kb = (c + 1) * 64;
            const size_t go = (size_t)lrow * (KEXT * 2) + kb + lseg;
            const size_t go2 = (size_t)(lrow + 64) * (KEXT * 2) + kb + lseg;
            CPASYNC16(sAb + nb * STAGE_BYTES + lrow * SPITCH + lseg, Ab + go);
            CPASYNC16(sAb + nb * STAGE_BYTES + (lrow + 64) * SPITCH + lseg, Ab + go2);
            CPASYNC16(sBb + nb * STAGE_BYTES + lrow * SPITCH + lseg, Bb + go);
            CPASYNC16(sBb + nb * STAGE_BYTES + (lrow + 64) * SPITCH + lseg, Bb + go2);
            CP_COMMIT();
            CP_WAIT1();
        } else {
            CP_WAIT0();
        }
        __syncthreads();

        const uint32_t aS = sAb + (c & 1) * STAGE_BYTES + aRowOff;
        const uint32_t bS = sBb + (c & 1) * STAGE_BYTES + bRowOff;
#pragma unroll
        for (int ks = 0; ks < 2; ks++) {
            uint32_t afr[4][4], bfr[2][4];
#pragma unroll
            for (int mf = 0; mf < 4; mf++)
                LDMX4(afr[mf][0], afr[mf][1], afr[mf][2], afr[mf][3],
                      aS + mf * (16 * SPITCH) + ks * 32);
#pragma unroll
            for (int n2 = 0; n2 < 2; n2++)
                LDMX4(bfr[n2][0], bfr[n2][1], bfr[n2][2], bfr[n2][3],
                      bS + n2 * (16 * SPITCH) + ks * 32);
#pragma unroll
            for (int mf = 0; mf < 4; mf++)
#pragma unroll
                for (int nf = 0; nf < 4; nf++)
                    MMA16816(acc[mf][nf], afr[mf],
                             bfr[nf >> 1][(nf & 1) * 2],
                             bfr[nf >> 1][(nf & 1) * 2 + 1]);
        }
        __syncthreads();
    }

    // epilogue: fragment rows (l>>2, l>>2+8), cols (l&3)*2
    const int rbase = tileM * 128 + wm * 64 + (l >> 2);
    const int cbase = tileN * 128 + wn * 32 + (l & 3) * 2;
#pragma unroll
    for (int mf = 0; mf < 4; mf++) {
#pragma unroll
        for (int nf = 0; nf < 4; nf++) {
            const int col = cbase + nf * 8;
            const float b0 = bias[col], b1 = bias[col + 1];
            const size_t r0 = (size_t)(rbase + mf * 16) * Ntot + col;
            const size_t r1 = r0 + (size_t)8 * Ntot;
            *reinterpret_cast<float2*>(C + r0) =
                make_float2(acc[mf][nf][0] + b0, acc[mf][nf][1] + b1);
            *reinterpret_cast<float2*>(C + r1) =
                make_float2(acc[mf][nf][2] + b0, acc[mf][nf][3] + b1);
        }
    }
}

// ---------------- attention: one block per (window, head) --------------------
#define QP 33
#define VP 34
#define SMEM_FLOATS (NW * QP * 2 + NW * VP + NW * NW + NW)
#define SMEM_ATTN  (SMEM_FLOATS * 4)

__global__ __launch_bounds__(256) void attn_kernel() {
    extern __shared__ float sm[];
    float* Qs = sm;
    float* Ks = Qs + NW * QP;
    float* Vs = Ks + NW * QP;
    float* Ss = Vs + NW * VP;
    float* invs = Ss + NW * NW;

    const int hh = blockIdx.x;
    const int b = blockIdx.y;
    const int tid = threadIdx.x;
    const float scale = 0.17677669529663687f;
    const size_t rowBase = (size_t)b * NW;

    {
        const float* bh = g_bias + hh * (NW * NW);
        for (int idx = tid; idx < NW * NW; idx += 256)
            Ss[idx] = bh[idx];
    }
    for (int idx = tid; idx < NW * HD; idx += 256) {
        int n = idx >> 5, dd = idx & 31;
        size_t g = (rowBase + n) * QKVN + hh * HD + dd;
        Qs[n * QP + dd] = g_qkv[g] * scale;
        Ks[n * QP + dd] = g_qkv[g + DIM];
        Vs[n * VP + dd] = g_qkv[g + 2 * DIM];
    }
    __syncthreads();

    const int tx = tid & 15;
    const int ty = tid >> 4;

    {
        float acc[9][9];
#pragma unroll
        for (int i = 0; i < 9; i++)
#pragma unroll
            for (int j = 0; j < 9; j++) acc[i][j] = 0.f;
#pragma unroll
        for (int k = 0; k < HD; k++) {
            float ra[9], rb[9];
#pragma unroll
            for (int i = 0; i < 9; i++) ra[i] = Qs[(ty * 9 + i) * QP + k];
#pragma unroll
            for (int j = 0; j < 9; j++) rb[j] = Ks[(tx * 9 + j) * QP + k];
#pragma unroll
            for (int i = 0; i < 9; i++)
#pragma unroll
                for (int j = 0; j < 9; j++)
                    acc[i][j] = fmaf(ra[i], rb[j], acc[i][j]);
        }
#pragma unroll
        for (int i = 0; i < 9; i++) {
            int n = ty * 9 + i;
#pragma unroll
            for (int j = 0; j < 9; j++)
                Ss[n * NW + tx * 9 + j] += acc[i][j];
        }
    }
    __syncthreads();

    {
        const int lane = tid & 31, w = tid >> 5;
        for (int r = w; r < NW; r += 8) {
            float mx = -1e30f;
            for (int m = lane; m < NW; m += 32) mx = fmaxf(mx, Ss[r * NW + m]);
#pragma unroll
            for (int o = 16; o > 0; o >>= 1)
                mx = fmaxf(mx, __shfl_xor_sync(0xffffffff, mx, o));
            float s = 0.f;
            for (int m = lane; m < NW; m += 32) {
                float e = __expf(Ss[r * NW + m] - mx);
                Ss[r * NW + m] = e;
                s += e;
            }
#pragma unroll
            for (int o = 16; o > 0; o >>= 1)
                s += __shfl_xor_sync(0xffffffff, s, o);
            if (lane == 0) invs[r] = 1.0f / s;
        }
    }
    __syncthreads();

    {
        float a0[9], a1[9];
#pragma unroll
        for (int i = 0; i < 9; i++) { a0[i] = 0.f; a1[i] = 0.f; }
#pragma unroll 4
        for (int m = 0; m < NW; m++) {
            float2 v = *reinterpret_cast<const float2*>(&Vs[m * VP + tx * 2]);
#pragma unroll
            for (int i = 0; i < 9; i++) {
                float p = Ss[(ty * 9 + i) * NW + m];
                a0[i] = fmaf(p, v.x, a0[i]);
                a1[i] = fmaf(p, v.y, a1[i]);
            }
        }
#pragma unroll
        for (int i = 0; i < 9; i++) {
            int n = ty * 9 + i;
            float iv = invs[n];
            float v0 = a0[i] * iv, v1 = a1[i] * iv;
            unsigned short h0, l0, h1, l1;
            bf_split(v0, h0, l0);
            bf_split(v1, h1, l1);
            __nv_bfloat16* base = g_attx + (rowBase + n) * KEXT + hh * HD + tx * 2;
            ushort2 hp = make_ushort2(h0, h1);
            ushort2 lp = make_ushort2(l0, l1);
            *reinterpret_cast<ushort2*>(base)       = hp;
            *reinterpret_cast<ushort2*>(base + 256) = lp;
            *reinterpret_cast<ushort2*>(base + 512) = hp;
        }
    }
}

// ---------------- launch ------------------------------------------------------
extern "C" void kernel_launch(void* const* d_in, const int* in_sizes, int n_in,
                              void* d_out, int out_size) {
    const float* x      = (const float*)d_in[0];
    const float* qkv_w  = (const float*)d_in[1];
    const float* qkv_b  = (const float*)d_in[2];
    const float* proj_w = (const float*)d_in[3];
    const float* proj_b = (const float*)d_in[4];
    const float* rpb    = (const float*)d_in[5];
    const int*   rel    = (const int*)d_in[6];
    float* out = (float*)d_out;

    float* qkvbuf = nullptr;
    __nv_bfloat16 *axp = nullptr, *attxp = nullptr, *bqp = nullptr, *bpp = nullptr;
    cudaGetSymbolAddress((void**)&qkvbuf, g_qkv);
    cudaGetSymbolAddress((void**)&axp,   g_ax);
    cudaGetSymbolAddress((void**)&attxp, g_attx);
    cudaGetSymbolAddress((void**)&bqp,   g_bq);
    cudaGetSymbolAddress((void**)&bpp,   g_bp);

    static bool attr_done = false;
    if (!attr_done) {
        cudaFuncSetAttribute(attn_kernel,
                             cudaFuncAttributeMaxDynamicSharedMemorySize, SMEM_ATTN);
        attr_done = true;
    }

    // conversions + bias table (independent)
    conv_x_kernel<<<(NTOK * 64) / 256, 256>>>(x);
    conv_w_kernel<<<(QKVN * 256 + 255) / 256, 256>>>(qkv_w, bqp, QKVN);
    conv_w_kernel<<<(DIM * 256 + 255) / 256, 256>>>(proj_w, bpp, DIM);
    build_bias_kernel<<<(NW * NW + 255) / 256, 256>>>(rpb, rel);

    // QKV GEMM: [294912 x 768] (K'=768) via mma.sync bf16 split-2
    gemm_mma_kernel<<<dim3(QKVN / 128, NTOK / 128), 256>>>(
        axp, bqp, qkv_b, qkvbuf, QKVN);

    // attention per (head, window)
    attn_kernel<<<dim3(NH, BnW), 256, SMEM_ATTN>>>();

    // proj GEMM: [294912 x 256] (K'=768) -> out
    gemm_mma_kernel<<<dim3(DIM / 128, NTOK / 128), 256>>>(
        attxp, bpp, proj_b, out, DIM);
}

// round 4
// speedup vs baseline: 2.0395x; 1.4633x over previous
#include <cuda_runtime.h>
#include <cuda_bf16.h>
#include <cstdint>
#include <cstddef>

#define BnW   2048
#define NW    144
#define DIM   256
#define NH    8
#define HD    32
#define NTOK  (BnW * NW)            /* 294912 */
#define QKVN  (3 * DIM)             /* 768 */
#define KEXT  768                   /* split-bf16 extended K */

// ---------------- scratch (device globals: allocation-free rule) -------------
__device__ float         g_qkv[(size_t)NTOK * QKVN];     // fp32 q|k|v
__device__ __nv_bfloat16 g_ax[(size_t)NTOK * KEXT];      // x split-ext [Ah|Al|Ah]
__device__ __nv_bfloat16 g_attx[(size_t)NTOK * KEXT];    // attn out split-ext
__device__ __nv_bfloat16 g_bq[(size_t)QKVN * KEXT];      // qkv_w ext  [Bh|Bh|Bl]
__device__ __nv_bfloat16 g_bp[(size_t)DIM * KEXT];       // proj_w ext
__device__ float         g_bias[NH * NW * NW];           // [h][n][m] RPB

// ======================= baseline-PTX tensor-core helpers ====================
__device__ __forceinline__ uint32_t smem_u32(const void* p) {
    uint32_t a;
    asm("{ .reg .u64 t; cvta.to.shared.u64 t, %1; cvt.u32.u64 %0, t; }"
        : "=r"(a) : "l"(p));
    return a;
}
#define LDMX4(r0, r1, r2, r3, addr) \
    asm volatile("ldmatrix.sync.aligned.m8n8.x4.shared.b16 {%0,%1,%2,%3}, [%4];" \
                 : "=r"(r0), "=r"(r1), "=r"(r2), "=r"(r3) : "r"(addr))
#define LDMX2(r0, r1, addr) \
    asm volatile("ldmatrix.sync.aligned.m8n8.x2.shared.b16 {%0,%1}, [%2];" \
                 : "=r"(r0), "=r"(r1) : "r"(addr))
#define MMA16816(d, a, b0, b1) \
    asm volatile("mma.sync.aligned.m16n8k16.row.col.f32.bf16.bf16.f32 " \
                 "{%0,%1,%2,%3}, {%4,%5,%6,%7}, {%8,%9}, {%0,%1,%2,%3};" \
                 : "+f"((d)[0]), "+f"((d)[1]), "+f"((d)[2]), "+f"((d)[3]) \
                 : "r"((a)[0]), "r"((a)[1]), "r"((a)[2]), "r"((a)[3]), \
                   "r"(b0), "r"(b1))
#define CPASYNC16(s, g) \
    asm volatile("cp.async.cg.shared.global [%0], [%1], 16;" :: "r"(s), "l"(g))
#define CP_COMMIT() asm volatile("cp.async.commit_group;" ::: "memory")
#define CP_WAIT1()  asm volatile("cp.async.wait_group 1;" ::: "memory")
#define CP_WAIT0()  asm volatile("cp.async.wait_group 0;" ::: "memory")

// ======================= split-bf16 helpers ==================================
__device__ __forceinline__ void bf_split(float f, unsigned short& h, unsigned short& l) {
    __nv_bfloat16 hb = __float2bfloat16(f);
    __nv_bfloat16 lb = __float2bfloat16(f - __bfloat162float(hb));
    h = __bfloat16_as_ushort(hb);
    l = __bfloat16_as_ushort(lb);
}

// x [NTOK,256] fp32 -> g_ax [NTOK,768] = [Ah|Al|Ah]
__global__ __launch_bounds__(256) void conv_x_kernel(const float* __restrict__ x) {
    size_t i = (size_t)blockIdx.x * 256 + threadIdx.x;   // over NTOK*64
    size_t row = i >> 6;
    int c4 = (int)(i & 63) * 4;
    float4 v = *reinterpret_cast<const float4*>(x + row * DIM + c4);
    ushort4 hv, lv;
    bf_split(v.x, hv.x, lv.x); bf_split(v.y, hv.y, lv.y);
    bf_split(v.z, hv.z, lv.z); bf_split(v.w, hv.w, lv.w);
    __nv_bfloat16* base = g_ax + row * KEXT;
    *reinterpret_cast<ushort4*>(base + c4)       = hv;
    *reinterpret_cast<ushort4*>(base + 256 + c4) = lv;
    *reinterpret_cast<ushort4*>(base + 512 + c4) = hv;
}

// w [256,N] fp32 -> Bext [N,768] = [Bh|Bh|Bl]
__global__ __launch_bounds__(256) void conv_w_kernel(const float* __restrict__ w,
                                                     __nv_bfloat16* __restrict__ Bext,
                                                     int N) {
    int i = blockIdx.x * 256 + threadIdx.x;   // over N*256
    if (i >= N * 256) return;
    int n = i >> 8, k = i & 255;
    unsigned short h, l;
    bf_split(w[k * N + n], h, l);
    Bext[(size_t)n * KEXT + k]       = __ushort_as_bfloat16(h);
    Bext[(size_t)n * KEXT + 256 + k] = __ushort_as_bfloat16(h);
    Bext[(size_t)n * KEXT + 512 + k] = __ushort_as_bfloat16(l);
}

// ---------------- bias build: bias[h][n][m] = rpb[rel[n][m]][h] --------------
__global__ __launch_bounds__(256) void build_bias_kernel(
    const float* __restrict__ rpb, const int* __restrict__ rel) {
    int idx = blockIdx.x * 256 + threadIdx.x;
    if (idx < NW * NW) {
        int r = rel[idx];
#pragma unroll
        for (int h = 0; h < NH; h++)
            g_bias[h * (NW * NW) + idx] = rpb[r * NH + h];
    }
}

// ======================= mma.sync GEMM: C = Aext @ Bext^T + bias =============
#define NCHUNK 24                       /* 768 / 32 */
#define SPITCH 80
#define STAGE_BYTES (128 * SPITCH)

__global__ __launch_bounds__(256) void gemm_mma_kernel(
    const __nv_bfloat16* __restrict__ Aext,
    const __nv_bfloat16* __restrict__ Bext,
    const float* __restrict__ bias,
    float* __restrict__ C, int Ntot) {
    __shared__ char sA[2 * STAGE_BYTES];
    __shared__ char sB[2 * STAGE_BYTES];

    const int tid = threadIdx.x;
    const int w = tid >> 5, l = tid & 31;
    const int wm = w & 1, wn = w >> 1;
    const int tileN = blockIdx.x, tileM = blockIdx.y;

    const uint32_t sAb = smem_u32(sA);
    const uint32_t sBb = smem_u32(sB);

    const char* Ab = reinterpret_cast<const char*>(Aext) +
                     (size_t)tileM * 128 * (KEXT * 2);
    const char* Bb = reinterpret_cast<const char*>(Bext) +
                     (size_t)tileN * 128 * (KEXT * 2);

    const int lrow = tid >> 2;
    const int lseg = (tid & 3) * 16;

    float acc[4][4][4];
#pragma unroll
    for (int mf = 0; mf < 4; mf++)
#pragma unroll
        for (int nf = 0; nf < 4; nf++)
#pragma unroll
            for (int r = 0; r < 4; r++) acc[mf][nf][r] = 0.f;

    {
        const size_t go = (size_t)lrow * (KEXT * 2) + lseg;
        const size_t go2 = (size_t)(lrow + 64) * (KEXT * 2) + lseg;
        CPASYNC16(sAb + lrow * SPITCH + lseg, Ab + go);
        CPASYNC16(sAb + (lrow + 64) * SPITCH + lseg, Ab + go2);
        CPASYNC16(sBb + lrow * SPITCH + lseg, Bb + go);
        CPASYNC16(sBb + (lrow + 64) * SPITCH + lseg, Bb + go2);
        CP_COMMIT();
    }

    const uint32_t aRowOff = (uint32_t)(wm * 64 + (l & 15)) * SPITCH + (l >> 4) * 16;
    const uint32_t bRowOff = (uint32_t)(wn * 32 + ((l >> 4) * 8 + (l & 7))) * SPITCH +
                             ((l >> 3) & 1) * 16;

    for (int c = 0; c < NCHUNK; c++) {
        if (c + 1 < NCHUNK) {
            const int nb = (c + 1) & 1;
            const int kb = (c + 1) * 64;
            const size_t go = (size_t)lrow * (KEXT * 2) + kb + lseg;
            const size_t go2 = (size_t)(lrow + 64) * (KEXT * 2) + kb + lseg;
            CPASYNC16(sAb + nb * STAGE_BYTES + lrow * SPITCH + lseg, Ab + go);
            CPASYNC16(sAb + nb * STAGE_BYTES + (lrow + 64) * SPITCH + lseg, Ab + go2);
            CPASYNC16(sBb + nb * STAGE_BYTES + lrow * SPITCH + lseg, Bb + go);
            CPASYNC16(sBb + nb * STAGE_BYTES + (lrow + 64) * SPITCH + lseg, Bb + go2);
            CP_COMMIT();
            CP_WAIT1();
        } else {
            CP_WAIT0();
        }
        __syncthreads();

        const uint32_t aS = sAb + (c & 1) * STAGE_BYTES + aRowOff;
        const uint32_t bS = sBb + (c & 1) * STAGE_BYTES + bRowOff;
#pragma unroll
        for (int ks = 0; ks < 2; ks++) {
            uint32_t afr[4][4], bfr[2][4];
#pragma unroll
            for (int mf = 0; mf < 4; mf++)
                LDMX4(afr[mf][0], afr[mf][1], afr[mf][2], afr[mf][3],
                      aS + mf * (16 * SPITCH) + ks * 32);
#pragma unroll
            for (int n2 = 0; n2 < 2; n2++)
                LDMX4(bfr[n2][0], bfr[n2][1], bfr[n2][2], bfr[n2][3],
                      bS + n2 * (16 * SPITCH) + ks * 32);
#pragma unroll
            for (int mf = 0; mf < 4; mf++)
#pragma unroll
                for (int nf = 0; nf < 4; nf++)
                    MMA16816(acc[mf][nf], afr[mf],
                             bfr[nf >> 1][(nf & 1) * 2],
                             bfr[nf >> 1][(nf & 1) * 2 + 1]);
        }
        __syncthreads();
    }

    const int rbase = tileM * 128 + wm * 64 + (l >> 2);
    const int cbase = tileN * 128 + wn * 32 + (l & 3) * 2;
#pragma unroll
    for (int mf = 0; mf < 4; mf++) {
#pragma unroll
        for (int nf = 0; nf < 4; nf++) {
            const int col = cbase + nf * 8;
            const float b0 = bias[col], b1 = bias[col + 1];
            const size_t r0 = (size_t)(rbase + mf * 16) * Ntot + col;
            const size_t r1 = r0 + (size_t)8 * Ntot;
            *reinterpret_cast<float2*>(C + r0) =
                make_float2(acc[mf][nf][0] + b0, acc[mf][nf][1] + b1);
            *reinterpret_cast<float2*>(C + r1) =
                make_float2(acc[mf][nf][2] + b0, acc[mf][nf][3] + b1);
        }
    }
}

// ======================= tensor-core attention ===============================
// block = (head h, window b, query-chunk qc of 48 rows); 128 threads, 4 warps.
// Qext [48][Qh|Ql]  pitch 144B;  Kext [144][Kh|Kl] pitch 144B
// Vt   [32][Vh(144)|Vl(144)]    pitch 592B
// Pext [48][Ph(144)|Pl(144)]    pitch 592B
#define QPITCH 144
#define KPITCH 144
#define VPITCH 592
#define PPITCH 592
#define OFF_Q   0
#define OFF_K   (48 * QPITCH)                    /* 6912  */
#define OFF_V   (OFF_K + 144 * KPITCH)           /* 27648 */
#define OFF_P   (OFF_V + 32 * VPITCH)            /* 46592 */
#define OFF_MX  (OFF_P + 48 * PPITCH)            /* 75008 */
#define OFF_SM2 (OFF_MX + 48 * 16)               /* 75776 */
#define SMEM_ATTN (OFF_SM2 + 48 * 16)            /* 76544 */

__global__ __launch_bounds__(128) void attn_tc_kernel() {
    extern __shared__ char sm[];
    const uint32_t sb = smem_u32(sm);
    const int tid = threadIdx.x, l = tid & 31, w = tid >> 5;
    const int h = blockIdx.x, b = blockIdx.y, qc = blockIdx.z;
    const int qbase = qc * 48;
    const size_t tokBase = (size_t)b * NW;
    const float scale = 0.17677669529663687f;

    // warp n8-tile quota: 5,5,4,4 (18 tiles = 144 keys)
    const int quota = (w < 2) ? 5 : 4;
    const int nb8 = (w < 2) ? w * 5 : 10 + (w - 2) * 4;

    // ---- build Qext (scaled, split) ----
    for (int idx = tid; idx < 48 * 8; idx += 128) {
        int r = idx >> 3, d4 = (idx & 7) * 4;
        float4 q = *reinterpret_cast<const float4*>(
            g_qkv + (tokBase + qbase + r) * QKVN + h * HD + d4);
        unsigned short h0, l0, h1, l1, h2, l2, h3, l3;
        bf_split(q.x * scale, h0, l0); bf_split(q.y * scale, h1, l1);
        bf_split(q.z * scale, h2, l2); bf_split(q.w * scale, h3, l3);
        char* base = sm + OFF_Q + r * QPITCH + d4 * 2;
        *reinterpret_cast<uint32_t*>(base)     = (uint32_t)h0 | ((uint32_t)h1 << 16);
        *reinterpret_cast<uint32_t*>(base + 4) = (uint32_t)h2 | ((uint32_t)h3 << 16);
        *reinterpret_cast<uint32_t*>(base + 64)     = (uint32_t)l0 | ((uint32_t)l1 << 16);
        *reinterpret_cast<uint32_t*>(base + 64 + 4) = (uint32_t)l2 | ((uint32_t)l3 << 16);
    }
    // ---- build Kext ----
    for (int idx = tid; idx < 144 * 8; idx += 128) {
        int r = idx >> 3, d4 = (idx & 7) * 4;
        float4 k = *reinterpret_cast<const float4*>(
            g_qkv + (tokBase + r) * QKVN + DIM + h * HD + d4);
        unsigned short h0, l0, h1, l1, h2, l2, h3, l3;
        bf_split(k.x, h0, l0); bf_split(k.y, h1, l1);
        bf_split(k.z, h2, l2); bf_split(k.w, h3, l3);
        char* base = sm + OFF_K + r * KPITCH + d4 * 2;
        *reinterpret_cast<uint32_t*>(base)     = (uint32_t)h0 | ((uint32_t)h1 << 16);
        *reinterpret_cast<uint32_t*>(base + 4) = (uint32_t)h2 | ((uint32_t)h3 << 16);
        *reinterpret_cast<uint32_t*>(base + 64)     = (uint32_t)l0 | ((uint32_t)l1 << 16);
        *reinterpret_cast<uint32_t*>(base + 64 + 4) = (uint32_t)l2 | ((uint32_t)l3 << 16);
    }
    // ---- build Vt (transposed, split) ----
    for (int idx = tid; idx < 144 * 8; idx += 128) {
        int m = idx >> 3, d4 = (idx & 7) * 4;
        float4 v = *reinterpret_cast<const float4*>(
            g_qkv + (tokBase + m) * QKVN + 2 * DIM + h * HD + d4);
        float vv[4] = {v.x, v.y, v.z, v.w};
#pragma unroll
        for (int j = 0; j < 4; j++) {
            unsigned short hh, ll;
            bf_split(vv[j], hh, ll);
            char* base = sm + OFF_V + (d4 + j) * VPITCH + 2 * m;
            *reinterpret_cast<unsigned short*>(base)       = hh;
            *reinterpret_cast<unsigned short*>(base + 288) = ll;
        }
    }
    __syncthreads();

    // ---- QK^T: S[48 x 144] = Qext @ Kext^T (3 split passes, k=32 each) ----
    float accS[3][5][4];
#pragma unroll
    for (int mt = 0; mt < 3; mt++)
#pragma unroll
        for (int j = 0; j < 5; j++)
#pragma unroll
            for (int e = 0; e < 4; e++) accS[mt][j][e] = 0.f;

    const uint32_t aBase = sb + OFF_Q + (l & 15) * QPITCH + (l >> 4) * 16;
    const uint32_t bBase = sb + OFF_K + (nb8 * 8 + (l & 7)) * KPITCH + ((l >> 3) & 1) * 16;
#pragma unroll
    for (int pass = 0; pass < 3; pass++) {
        const int aoff = (pass == 1) ? 64 : 0;
        const int boff = (pass == 2) ? 64 : 0;
#pragma unroll
        for (int ks = 0; ks < 2; ks++) {
            uint32_t afr[3][4];
#pragma unroll
            for (int mt = 0; mt < 3; mt++)
                LDMX4(afr[mt][0], afr[mt][1], afr[mt][2], afr[mt][3],
                      aBase + mt * (16 * QPITCH) + aoff + ks * 32);
            uint32_t bfr[5][2];
#pragma unroll
            for (int j = 0; j < 5; j++)
                if (j < quota)
                    LDMX2(bfr[j][0], bfr[j][1],
                          bBase + j * (8 * KPITCH) + boff + ks * 32);
#pragma unroll
            for (int mt = 0; mt < 3; mt++)
#pragma unroll
                for (int j = 0; j < 5; j++)
                    if (j < quota)
                        MMA16816(accS[mt][j], afr[mt], bfr[j][0], bfr[j][1]);
        }
    }

    // ---- bias add + row max ----
    const float* bh = g_bias + h * (NW * NW);
    float rmax[3][2];
#pragma unroll
    for (int mt = 0; mt < 3; mt++) { rmax[mt][0] = -1e30f; rmax[mt][1] = -1e30f; }
#pragma unroll
    for (int mt = 0; mt < 3; mt++) {
        const int r = qbase + mt * 16 + (l >> 2);
#pragma unroll
        for (int j = 0; j < 5; j++)
            if (j < quota) {
                const int c = (nb8 + j) * 8 + (l & 3) * 2;
                float2 b0 = *reinterpret_cast<const float2*>(bh + r * NW + c);
                float2 b1 = *reinterpret_cast<const float2*>(bh + (r + 8) * NW + c);
                accS[mt][j][0] += b0.x; accS[mt][j][1] += b0.y;
                accS[mt][j][2] += b1.x; accS[mt][j][3] += b1.y;
                rmax[mt][0] = fmaxf(rmax[mt][0], fmaxf(accS[mt][j][0], accS[mt][j][1]));
                rmax[mt][1] = fmaxf(rmax[mt][1], fmaxf(accS[mt][j][2], accS[mt][j][3]));
            }
    }
#pragma unroll
    for (int mt = 0; mt < 3; mt++) {
#pragma unroll
        for (int o = 1; o <= 2; o <<= 1) {
            rmax[mt][0] = fmaxf(rmax[mt][0], __shfl_xor_sync(0xffffffff, rmax[mt][0], o));
            rmax[mt][1] = fmaxf(rmax[mt][1], __shfl_xor_sync(0xffffffff, rmax[mt][1], o));
        }
    }
    float* mx = reinterpret_cast<float*>(sm + OFF_MX);
    if ((l & 3) == 0) {
#pragma unroll
        for (int mt = 0; mt < 3; mt++) {
            mx[(mt * 16 + (l >> 2)) * 4 + w]     = rmax[mt][0];
            mx[(mt * 16 + 8 + (l >> 2)) * 4 + w] = rmax[mt][1];
        }
    }
    __syncthreads();

    // ---- exp + row sum ----
    float gmax[3][2], rsum[3][2];
#pragma unroll
    for (int mt = 0; mt < 3; mt++) {
        float4 m0 = *reinterpret_cast<const float4*>(mx + (mt * 16 + (l >> 2)) * 4);
        float4 m1 = *reinterpret_cast<const float4*>(mx + (mt * 16 + 8 + (l >> 2)) * 4);
        gmax[mt][0] = fmaxf(fmaxf(m0.x, m0.y), fmaxf(m0.z, m0.w));
        gmax[mt][1] = fmaxf(fmaxf(m1.x, m1.y), fmaxf(m1.z, m1.w));
        rsum[mt][0] = 0.f; rsum[mt][1] = 0.f;
    }
#pragma unroll
    for (int mt = 0; mt < 3; mt++)
#pragma unroll
        for (int j = 0; j < 5; j++)
            if (j < quota) {
                accS[mt][j][0] = __expf(accS[mt][j][0] - gmax[mt][0]);
                accS[mt][j][1] = __expf(accS[mt][j][1] - gmax[mt][0]);
                accS[mt][j][2] = __expf(accS[mt][j][2] - gmax[mt][1]);
                accS[mt][j][3] = __expf(accS[mt][j][3] - gmax[mt][1]);
                rsum[mt][0] += accS[mt][j][0] + accS[mt][j][1];
                rsum[mt][1] += accS[mt][j][2] + accS[mt][j][3];
            }
#pragma unroll
    for (int mt = 0; mt < 3; mt++) {
#pragma unroll
        for (int o = 1; o <= 2; o <<= 1) {
            rsum[mt][0] += __shfl_xor_sync(0xffffffff, rsum[mt][0], o);
            rsum[mt][1] += __shfl_xor_sync(0xffffffff, rsum[mt][1], o);
        }
    }
    float* sm2 = reinterpret_cast<float*>(sm + OFF_SM2);
    if ((l & 3) == 0) {
#pragma unroll
        for (int mt = 0; mt < 3; mt++) {
            sm2[(mt * 16 + (l >> 2)) * 4 + w]     = rsum[mt][0];
            sm2[(mt * 16 + 8 + (l >> 2)) * 4 + w] = rsum[mt][1];
        }
    }
    __syncthreads();

    // ---- normalize, split, store Pext ----
    float inv[3][2];
#pragma unroll
    for (int mt = 0; mt < 3; mt++) {
        float4 s0 = *reinterpret_cast<const float4*>(sm2 + (mt * 16 + (l >> 2)) * 4);
        float4 s1 = *reinterpret_cast<const float4*>(sm2 + (mt * 16 + 8 + (l >> 2)) * 4);
        inv[mt][0] = 1.0f / (s0.x + s0.y + s0.z + s0.w);
        inv[mt][1] = 1.0f / (s1.x + s1.y + s1.z + s1.w);
    }
#pragma unroll
    for (int mt = 0; mt < 3; mt++) {
        const int rr = mt * 16 + (l >> 2);
#pragma unroll
        for (int j = 0; j < 5; j++)
            if (j < quota) {
                const int cb = (nb8 + j) * 8 + (l & 3) * 2;
                unsigned short h0, l0, h1, l1, h2, l2, h3, l3;
                bf_split(accS[mt][j][0] * inv[mt][0], h0, l0);
                bf_split(accS[mt][j][1] * inv[mt][0], h1, l1);
                bf_split(accS[mt][j][2] * inv[mt][1], h2, l2);
                bf_split(accS[mt][j][3] * inv[mt][1], h3, l3);
                char* p0 = sm + OFF_P + rr * PPITCH + 2 * cb;
                char* p1 = sm + OFF_P + (rr + 8) * PPITCH + 2 * cb;
                *reinterpret_cast<uint32_t*>(p0)       = (uint32_t)h0 | ((uint32_t)h1 << 16);
                *reinterpret_cast<uint32_t*>(p0 + 288) = (uint32_t)l0 | ((uint32_t)l1 << 16);
                *reinterpret_cast<uint32_t*>(p1)       = (uint32_t)h2 | ((uint32_t)h3 << 16);
                *reinterpret_cast<uint32_t*>(p1 + 288) = (uint32_t)l2 | ((uint32_t)l3 << 16);
            }
    }
    __syncthreads();

    // ---- PV: O[48 x 32] = P @ V (3 split passes, k=144 each) ----
    float accO[3][4];
#pragma unroll
    for (int mt = 0; mt < 3; mt++)
#pragma unroll
        for (int e = 0; e < 4; e++) accO[mt][e] = 0.f;

    const uint32_t pBase = sb + OFF_P + (l & 15) * PPITCH + (l >> 4) * 16;
    const uint32_t vBase = sb + OFF_V + (w * 8 + (l & 7)) * VPITCH + ((l >> 3) & 1) * 16;
#pragma unroll
    for (int pass = 0; pass < 3; pass++) {
        const int poff = (pass == 1) ? 288 : 0;
        const int voff = (pass == 2) ? 288 : 0;
#pragma unroll
        for (int ks = 0; ks < 9; ks++) {
            uint32_t afr[3][4];
#pragma unroll
            for (int mt = 0; mt < 3; mt++)
                LDMX4(afr[mt][0], afr[mt][1], afr[mt][2], afr[mt][3],
                      pBase + mt * (16 * PPITCH) + poff + ks * 32);
            uint32_t b0, b1;
            LDMX2(b0, b1, vBase + voff + ks * 32);
#pragma unroll
            for (int mt = 0; mt < 3; mt++)
                MMA16816(accO[mt], afr[mt], b0, b1);
        }
    }

    // ---- write O in split-ext layout to g_attx ----
#pragma unroll
    for (int mt = 0; mt < 3; mt++) {
        const int r = qbase + mt * 16 + (l >> 2);
        const int d = w * 8 + (l & 3) * 2;
        unsigned short h0, l0, h1, l1, h2, l2, h3, l3;
        bf_split(accO[mt][0], h0, l0); bf_split(accO[mt][1], h1, l1);
        bf_split(accO[mt][2], h2, l2); bf_split(accO[mt][3], h3, l3);
        uint32_t hp0 = (uint32_t)h0 | ((uint32_t)h1 << 16);
        uint32_t lp0 = (uint32_t)l0 | ((uint32_t)l1 << 16);
        uint32_t hp1 = (uint32_t)h2 | ((uint32_t)h3 << 16);
        uint32_t lp1 = (uint32_t)l2 | ((uint32_t)l3 << 16);
        __nv_bfloat16* o0 = g_attx + (tokBase + r) * KEXT + h * HD + d;
        __nv_bfloat16* o1 = g_attx + (tokBase + r + 8) * KEXT + h * HD + d;
        *reinterpret_cast<uint32_t*>(o0)       = hp0;
        *reinterpret_cast<uint32_t*>(o0 + 256) = lp0;
        *reinterpret_cast<uint32_t*>(o0 + 512) = hp0;
        *reinterpret_cast<uint32_t*>(o1)       = hp1;
        *reinterpret_cast<uint32_t*>(o1 + 256) = lp1;
        *reinterpret_cast<uint32_t*>(o1 + 512) = hp1;
    }
}

// ---------------- launch ------------------------------------------------------
extern "C" void kernel_launch(void* const* d_in, const int* in_sizes, int n_in,
                              void* d_out, int out_size) {
    const float* x      = (const float*)d_in[0];
    const float* qkv_w  = (const float*)d_in[1];
    const float* qkv_b  = (const float*)d_in[2];
    const float* proj_w = (const float*)d_in[3];
    const float* proj_b = (const float*)d_in[4];
    const float* rpb    = (const float*)d_in[5];
    const int*   rel    = (const int*)d_in[6];
    float* out = (float*)d_out;

    float* qkvbuf = nullptr;
    __nv_bfloat16 *axp = nullptr, *attxp = nullptr, *bqp = nullptr, *bpp = nullptr;
    cudaGetSymbolAddress((void**)&qkvbuf, g_qkv);
    cudaGetSymbolAddress((void**)&axp,   g_ax);
    cudaGetSymbolAddress((void**)&attxp, g_attx);
    cudaGetSymbolAddress((void**)&bqp,   g_bq);
    cudaGetSymbolAddress((void**)&bpp,   g_bp);

    static bool attr_done = false;
    if (!attr_done) {
        cudaFuncSetAttribute(attn_tc_kernel,
                             cudaFuncAttributeMaxDynamicSharedMemorySize, SMEM_ATTN);
        attr_done = true;
    }

    // conversions + bias table (independent)
    conv_x_kernel<<<(NTOK * 64) / 256, 256>>>(x);
    conv_w_kernel<<<(QKVN * 256 + 255) / 256, 256>>>(qkv_w, bqp, QKVN);
    conv_w_kernel<<<(DIM * 256 + 255) / 256, 256>>>(proj_w, bpp, DIM);
    build_bias_kernel<<<(NW * NW + 255) / 256, 256>>>(rpb, rel);

    // QKV GEMM: [294912 x 768] (K'=768) via mma.sync bf16 split-2
    gemm_mma_kernel<<<dim3(QKVN / 128, NTOK / 128), 256>>>(
        axp, bqp, qkv_b, qkvbuf, QKVN);

    // tensor-core attention: (head, window, query-chunk)
    attn_tc_kernel<<<dim3(NH, BnW, 3), 128, SMEM_ATTN>>>();

    // proj GEMM: [294912 x 256] (K'=768) -> out
    gemm_mma_kernel<<<dim3(DIM / 128, NTOK / 128), 256>>>(
        attxp, bpp, proj_b, out, DIM);
}

// round 5
// speedup vs baseline: 2.3079x; 1.1316x over previous
#include <cuda_runtime.h>
#include <cuda_bf16.h>
#include <cstdint>
#include <cstddef>

#define BnW   2048
#define NW    144
#define DIM   256
#define NH    8
#define HD    32
#define NTOK  (BnW * NW)            /* 294912 */
#define QKVN  (3 * DIM)             /* 768 */
#define KSTORE 512                  /* split-bf16 stored K: [hi|lo] */
#define NCHUNK 24                   /* effective K' = 768 in 32-elem chunks */
#define SCALE 0.17677669529663687f

// ---------------- scratch (device globals: allocation-free rule) -------------
__device__ uint32_t      g_qkv[(size_t)NTOK * QKVN];     // packed (hi|lo) bf16 q|k|v
__device__ __nv_bfloat16 g_ax[(size_t)NTOK * KSTORE];    // x ext [Ah|Al]
__device__ __nv_bfloat16 g_attx[(size_t)NTOK * KSTORE];  // attn out ext [Oh|Ol]
__device__ __nv_bfloat16 g_bq[(size_t)QKVN * KSTORE];    // qkv_w ext [Bh|Bl] (q-cols scaled)
__device__ __nv_bfloat16 g_bp[(size_t)DIM * KSTORE];     // proj_w ext
__device__ float         g_sbias[QKVN];                  // scaled qkv bias
__device__ float         g_bias[NH * NW * NW];           // [h][n][m] RPB

// ======================= baseline-PTX tensor-core helpers ====================
__device__ __forceinline__ uint32_t smem_u32(const void* p) {
    uint32_t a;
    asm("{ .reg .u64 t; cvta.to.shared.u64 t, %1; cvt.u32.u64 %0, t; }"
        : "=r"(a) : "l"(p));
    return a;
}
#define LDMX4(r0, r1, r2, r3, addr) \
    asm volatile("ldmatrix.sync.aligned.m8n8.x4.shared.b16 {%0,%1,%2,%3}, [%4];" \
                 : "=r"(r0), "=r"(r1), "=r"(r2), "=r"(r3) : "r"(addr))
#define LDMX2(r0, r1, addr) \
    asm volatile("ldmatrix.sync.aligned.m8n8.x2.shared.b16 {%0,%1}, [%2];" \
                 : "=r"(r0), "=r"(r1) : "r"(addr))
#define MMA16816(d, a, b0, b1) \
    asm volatile("mma.sync.aligned.m16n8k16.row.col.f32.bf16.bf16.f32 " \
                 "{%0,%1,%2,%3}, {%4,%5,%6,%7}, {%8,%9}, {%0,%1,%2,%3};" \
                 : "+f"((d)[0]), "+f"((d)[1]), "+f"((d)[2]), "+f"((d)[3]) \
                 : "r"((a)[0]), "r"((a)[1]), "r"((a)[2]), "r"((a)[3]), \
                   "r"(b0), "r"(b1))
#define CPASYNC16(s, g) \
    asm volatile("cp.async.cg.shared.global [%0], [%1], 16;" :: "r"(s), "l"(g))
#define CP_COMMIT() asm volatile("cp.async.commit_group;" ::: "memory")
#define CP_WAIT1()  asm volatile("cp.async.wait_group 1;" ::: "memory")
#define CP_WAIT0()  asm volatile("cp.async.wait_group 0;" ::: "memory")

// ======================= split-bf16 helpers ==================================
__device__ __forceinline__ void bf_split(float f, unsigned short& h, unsigned short& l) {
    __nv_bfloat16 hb = __float2bfloat16(f);
    __nv_bfloat16 lb = __float2bfloat16(f - __bfloat162float(hb));
    h = __bfloat16_as_ushort(hb);
    l = __bfloat16_as_ushort(lb);
}
__device__ __forceinline__ uint32_t pack_hl(float f) {
    unsigned short h, l;
    bf_split(f, h, l);
    return (uint32_t)h | ((uint32_t)l << 16);
}

// x [NTOK,256] fp32 -> g_ax [NTOK,512] = [Ah|Al]
__global__ __launch_bounds__(256) void conv_x_kernel(const float* __restrict__ x) {
    size_t i = (size_t)blockIdx.x * 256 + threadIdx.x;   // over NTOK*64
    size_t row = i >> 6;
    int c4 = (int)(i & 63) * 4;
    float4 v = *reinterpret_cast<const float4*>(x + row * DIM + c4);
    ushort4 hv, lv;
    bf_split(v.x, hv.x, lv.x); bf_split(v.y, hv.y, lv.y);
    bf_split(v.z, hv.z, lv.z); bf_split(v.w, hv.w, lv.w);
    __nv_bfloat16* base = g_ax + row * KSTORE;
    *reinterpret_cast<ushort4*>(base + c4)       = hv;
    *reinterpret_cast<ushort4*>(base + 256 + c4) = lv;
}

// w [256,N] fp32 -> Bext [N,512] = [Bh|Bl]; first nscale output cols scaled
__global__ __launch_bounds__(256) void conv_w_kernel(const float* __restrict__ w,
                                                     __nv_bfloat16* __restrict__ Bext,
                                                     int N, int nscale) {
    int i = blockIdx.x * 256 + threadIdx.x;   // over N*256
    if (i >= N * 256) return;
    int n = i >> 8, k = i & 255;
    float val = w[k * N + n];
    if (n < nscale) val *= SCALE;
    unsigned short h, l;
    bf_split(val, h, l);
    Bext[(size_t)n * KSTORE + k]       = __ushort_as_bfloat16(h);
    Bext[(size_t)n * KSTORE + 256 + k] = __ushort_as_bfloat16(l);
}

__global__ void prep_bias_kernel(const float* __restrict__ qkv_b) {
    int i = blockIdx.x * 256 + threadIdx.x;
    if (i < QKVN) g_sbias[i] = qkv_b[i] * (i < DIM ? SCALE : 1.0f);
}

// bias[h][n][m] = rpb[rel[n][m]][h]
__global__ __launch_bounds__(256) void build_bias_kernel(
    const float* __restrict__ rpb, const int* __restrict__ rel) {
    int idx = blockIdx.x * 256 + threadIdx.x;
    if (idx < NW * NW) {
        int r = rel[idx];
#pragma unroll
        for (int h = 0; h < NH; h++)
            g_bias[h * (NW * NW) + idx] = rpb[r * NH + h];
    }
}

// ======================= mma.sync GEMM: C = Aext @ Bext^T + bias =============
// A [M,512] / B [N,512] bf16; effective K'=768 via chunk remap:
//   c<8:  Ah(c)    x Bh(c)      c in 8..15: Al(c) x Bh(c-8)
//   c>=16: Ah(c-16) x Bl(c-8)
// 3-stage cp.async pipeline, tile 128x128x32, 8 warps (2M x 4N).
#define SPITCH 80
#define STAGE_BYTES (128 * SPITCH)
#define SMEM_GEMM (6 * STAGE_BYTES)       /* 61440 */

template <bool PACK>
__global__ __launch_bounds__(256, 2) void gemm_mma_kernel(
    const __nv_bfloat16* __restrict__ Aext,
    const __nv_bfloat16* __restrict__ Bext,
    const float* __restrict__ bias,
    void* __restrict__ Cout, int Ntot) {
    extern __shared__ char gsm[];
    const uint32_t sAb = smem_u32(gsm);
    const uint32_t sBb = sAb + 3 * STAGE_BYTES;

    const int tid = threadIdx.x;
    const int w = tid >> 5, l = tid & 31;
    const int wm = w & 1, wn = w >> 1;
    const int tileN = blockIdx.x, tileM = blockIdx.y;

    const char* Ab = reinterpret_cast<const char*>(Aext) +
                     (size_t)tileM * 128 * (KSTORE * 2);
    const char* Bb = reinterpret_cast<const char*>(Bext) +
                     (size_t)tileN * 128 * (KSTORE * 2);

    const int lrow = tid >> 2;
    const int lseg = (tid & 3) * 16;

    float acc[4][4][4];
#pragma unroll
    for (int mf = 0; mf < 4; mf++)
#pragma unroll
        for (int nf = 0; nf < 4; nf++)
#pragma unroll
            for (int r = 0; r < 4; r++) acc[mf][nf][r] = 0.f;

    // chunk issue helper (inlined twice below)
#define ISSUE_CHUNK(cc) do {                                                      \
        const int _c = (cc);                                                      \
        const int _aoff = (_c < 16) ? _c : _c - 16;                               \
        const int _boff = (_c < 8) ? _c : _c - 8;                                 \
        const int _buf = _c % 3;                                                  \
        const size_t _gaA = (size_t)lrow * (KSTORE * 2) + _aoff * 64 + lseg;      \
        const size_t _gaA2 = (size_t)(lrow + 64) * (KSTORE * 2) + _aoff * 64 + lseg; \
        const size_t _gaB = (size_t)lrow * (KSTORE * 2) + _boff * 64 + lseg;      \
        const size_t _gaB2 = (size_t)(lrow + 64) * (KSTORE * 2) + _boff * 64 + lseg; \
        CPASYNC16(sAb + _buf * STAGE_BYTES + lrow * SPITCH + lseg, Ab + _gaA);    \
        CPASYNC16(sAb + _buf * STAGE_BYTES + (lrow + 64) * SPITCH + lseg, Ab + _gaA2); \
        CPASYNC16(sBb + _buf * STAGE_BYTES + lrow * SPITCH + lseg, Bb + _gaB);    \
        CPASYNC16(sBb + _buf * STAGE_BYTES + (lrow + 64) * SPITCH + lseg, Bb + _gaB2); \
        CP_COMMIT();                                                              \
    } while (0)

    ISSUE_CHUNK(0);
    ISSUE_CHUNK(1);

    const uint32_t aRowOff = (uint32_t)(wm * 64 + (l & 15)) * SPITCH + (l >> 4) * 16;
    const uint32_t bRowOff = (uint32_t)(wn * 32 + ((l >> 4) * 8 + (l & 7))) * SPITCH +
                             ((l >> 3) & 1) * 16;

    for (int c = 0; c < NCHUNK; c++) {
        if (c < NCHUNK - 1) CP_WAIT1(); else CP_WAIT0();
        __syncthreads();
        if (c + 2 < NCHUNK) ISSUE_CHUNK(c + 2);

        const uint32_t stg = (uint32_t)(c % 3) * STAGE_BYTES;
        const uint32_t aS = sAb + stg + aRowOff;
        const uint32_t bS = sBb + stg + bRowOff;
#pragma unroll
        for (int ks = 0; ks < 2; ks++) {
            uint32_t afr[4][4], bfr[2][4];
#pragma unroll
            for (int mf = 0; mf < 4; mf++)
                LDMX4(afr[mf][0], afr[mf][1], afr[mf][2], afr[mf][3],
                      aS + mf * (16 * SPITCH) + ks * 32);
#pragma unroll
            for (int n2 = 0; n2 < 2; n2++)
                LDMX4(bfr[n2][0], bfr[n2][1], bfr[n2][2], bfr[n2][3],
                      bS + n2 * (16 * SPITCH) + ks * 32);
#pragma unroll
            for (int mf = 0; mf < 4; mf++)
#pragma unroll
                for (int nf = 0; nf < 4; nf++)
                    MMA16816(acc[mf][nf], afr[mf],
                             bfr[nf >> 1][(nf & 1) * 2],
                             bfr[nf >> 1][(nf & 1) * 2 + 1]);
        }
    }
#undef ISSUE_CHUNK

    const int rbase = tileM * 128 + wm * 64 + (l >> 2);
    const int cbase = tileN * 128 + wn * 32 + (l & 3) * 2;
#pragma unroll
    for (int mf = 0; mf < 4; mf++) {
#pragma unroll
        for (int nf = 0; nf < 4; nf++) {
            const int col = cbase + nf * 8;
            const float b0 = bias[col], b1 = bias[col + 1];
            const size_t r0 = (size_t)(rbase + mf * 16) * Ntot + col;
            const size_t r1 = r0 + (size_t)8 * Ntot;
            if (PACK) {
                uint32_t* C = reinterpret_cast<uint32_t*>(Cout);
                *reinterpret_cast<uint2*>(C + r0) =
                    make_uint2(pack_hl(acc[mf][nf][0] + b0), pack_hl(acc[mf][nf][1] + b1));
                *reinterpret_cast<uint2*>(C + r1) =
                    make_uint2(pack_hl(acc[mf][nf][2] + b0), pack_hl(acc[mf][nf][3] + b1));
            } else {
                float* C = reinterpret_cast<float*>(Cout);
                *reinterpret_cast<float2*>(C + r0) =
                    make_float2(acc[mf][nf][0] + b0, acc[mf][nf][1] + b1);
                *reinterpret_cast<float2*>(C + r1) =
                    make_float2(acc[mf][nf][2] + b0, acc[mf][nf][3] + b1);
            }
        }
    }
}

// ======================= tensor-core attention ===============================
// block = (head h, window b, query-chunk qc of 48 rows); 128 threads, 4 warps.
#define QPITCH 144
#define KPITCH 144
#define VPITCH 592
#define PPITCH 592
#define OFF_Q   0
#define OFF_K   (48 * QPITCH)
#define OFF_V   (OFF_K + 144 * KPITCH)
#define OFF_P   (OFF_V + 32 * VPITCH)
#define OFF_MX  (OFF_P + 48 * PPITCH)
#define OFF_SM2 (OFF_MX + 48 * 16)
#define SMEM_ATTN (OFF_SM2 + 48 * 16)

__global__ __launch_bounds__(128) void attn_tc_kernel() {
    extern __shared__ char sm[];
    const uint32_t sb = smem_u32(sm);
    const int tid = threadIdx.x, l = tid & 31, w = tid >> 5;
    const int h = blockIdx.x, b = blockIdx.y, qc = blockIdx.z;
    const int qbase = qc * 48;
    const size_t tokBase = (size_t)b * NW;

    const int quota = (w < 2) ? 5 : 4;
    const int nb8 = (w < 2) ? w * 5 : 10 + (w - 2) * 4;

    // ---- stage Q (packed -> [Qh|Ql] rows), scale pre-folded ----
    for (int idx = tid; idx < 48 * 8; idx += 128) {
        int r = idx >> 3, d4 = (idx & 7) * 4;
        uint4 e = *reinterpret_cast<const uint4*>(
            g_qkv + (tokBase + qbase + r) * QKVN + h * HD + d4);
        char* base = sm + OFF_Q + r * QPITCH + d4 * 2;
        *reinterpret_cast<uint32_t*>(base)      = __byte_perm(e.x, e.y, 0x5410);
        *reinterpret_cast<uint32_t*>(base + 4)  = __byte_perm(e.z, e.w, 0x5410);
        *reinterpret_cast<uint32_t*>(base + 64) = __byte_perm(e.x, e.y, 0x7632);
        *reinterpret_cast<uint32_t*>(base + 68) = __byte_perm(e.z, e.w, 0x7632);
    }
    // ---- stage K ----
    for (int idx = tid; idx < 144 * 8; idx += 128) {
        int r = idx >> 3, d4 = (idx & 7) * 4;
        uint4 e = *reinterpret_cast<const uint4*>(
            g_qkv + (tokBase + r) * QKVN + DIM + h * HD + d4);
        char* base = sm + OFF_K + r * KPITCH + d4 * 2;
        *reinterpret_cast<uint32_t*>(base)      = __byte_perm(e.x, e.y, 0x5410);
        *reinterpret_cast<uint32_t*>(base + 4)  = __byte_perm(e.z, e.w, 0x5410);
        *reinterpret_cast<uint32_t*>(base + 64) = __byte_perm(e.x, e.y, 0x7632);
        *reinterpret_cast<uint32_t*>(base + 68) = __byte_perm(e.z, e.w, 0x7632);
    }
    // ---- stage V transposed ----
    for (int idx = tid; idx < 144 * 8; idx += 128) {
        int m = idx >> 3, d4 = (idx & 7) * 4;
        uint4 e = *reinterpret_cast<const uint4*>(
            g_qkv + (tokBase + m) * QKVN + 2 * DIM + h * HD + d4);
        uint32_t ev[4] = {e.x, e.y, e.z, e.w};
#pragma unroll
        for (int j = 0; j < 4; j++) {
            char* base = sm + OFF_V + (d4 + j) * VPITCH + 2 * m;
            *reinterpret_cast<unsigned short*>(base)       = (unsigned short)ev[j];
            *reinterpret_cast<unsigned short*>(base + 288) = (unsigned short)(ev[j] >> 16);
        }
    }
    __syncthreads();

    // ---- QK^T: S[48 x 144] (3 split passes, k=32 each) ----
    float accS[3][5][4];
#pragma unroll
    for (int mt = 0; mt < 3; mt++)
#pragma unroll
        for (int j = 0; j < 5; j++)
#pragma unroll
            for (int e = 0; e < 4; e++) accS[mt][j][e] = 0.f;

    const uint32_t aBase = sb + OFF_Q + (l & 15) * QPITCH + (l >> 4) * 16;
    const uint32_t bBase = sb + OFF_K + (nb8 * 8 + (l & 7)) * KPITCH + ((l >> 3) & 1) * 16;
#pragma unroll
    for (int pass = 0; pass < 3; pass++) {
        const int aoff = (pass == 1) ? 64 : 0;
        const int boff = (pass == 2) ? 64 : 0;
#pragma unroll
        for (int ks = 0; ks < 2; ks++) {
            uint32_t afr[3][4];
#pragma unroll
            for (int mt = 0; mt < 3; mt++)
                LDMX4(afr[mt][0], afr[mt][1], afr[mt][2], afr[mt][3],
                      aBase + mt * (16 * QPITCH) + aoff + ks * 32);
            uint32_t bfr[5][2];
#pragma unroll
            for (int j = 0; j < 5; j++)
                if (j < quota)
                    LDMX2(bfr[j][0], bfr[j][1],
                          bBase + j * (8 * KPITCH) + boff + ks * 32);
#pragma unroll
            for (int mt = 0; mt < 3; mt++)
#pragma unroll
                for (int j = 0; j < 5; j++)
                    if (j < quota)
                        MMA16816(accS[mt][j], afr[mt], bfr[j][0], bfr[j][1]);
        }
    }

    // ---- bias add + row max ----
    const float* bh = g_bias + h * (NW * NW);
    float rmax[3][2];
#pragma unroll
    for (int mt = 0; mt < 3; mt++) { rmax[mt][0] = -1e30f; rmax[mt][1] = -1e30f; }
#pragma unroll
    for (int mt = 0; mt < 3; mt++) {
        const int r = qbase + mt * 16 + (l >> 2);
#pragma unroll
        for (int j = 0; j < 5; j++)
            if (j < quota) {
                const int c = (nb8 + j) * 8 + (l & 3) * 2;
                float2 b0 = *reinterpret_cast<const float2*>(bh + r * NW + c);
                float2 b1 = *reinterpret_cast<const float2*>(bh + (r + 8) * NW + c);
                accS[mt][j][0] += b0.x; accS[mt][j][1] += b0.y;
                accS[mt][j][2] += b1.x; accS[mt][j][3] += b1.y;
                rmax[mt][0] = fmaxf(rmax[mt][0], fmaxf(accS[mt][j][0], accS[mt][j][1]));
                rmax[mt][1] = fmaxf(rmax[mt][1], fmaxf(accS[mt][j][2], accS[mt][j][3]));
            }
    }
#pragma unroll
    for (int mt = 0; mt < 3; mt++) {
#pragma unroll
        for (int o = 1; o <= 2; o <<= 1) {
            rmax[mt][0] = fmaxf(rmax[mt][0], __shfl_xor_sync(0xffffffff, rmax[mt][0], o));
            rmax[mt][1] = fmaxf(rmax[mt][1], __shfl_xor_sync(0xffffffff, rmax[mt][1], o));
        }
    }
    float* mx = reinterpret_cast<float*>(sm + OFF_MX);
    if ((l & 3) == 0) {
#pragma unroll
        for (int mt = 0; mt < 3; mt++) {
            mx[(mt * 16 + (l >> 2)) * 4 + w]     = rmax[mt][0];
            mx[(mt * 16 + 8 + (l >> 2)) * 4 + w] = rmax[mt][1];
        }
    }
    __syncthreads();

    // ---- exp + row sum ----
    float gmax[3][2], rsum[3][2];
#pragma unroll
    for (int mt = 0; mt < 3; mt++) {
        float4 m0 = *reinterpret_cast<const float4*>(mx + (mt * 16 + (l >> 2)) * 4);
        float4 m1 = *reinterpret_cast<const float4*>(mx + (mt * 16 + 8 + (l >> 2)) * 4);
        gmax[mt][0] = fmaxf(fmaxf(m0.x, m0.y), fmaxf(m0.z, m0.w));
        gmax[mt][1] = fmaxf(fmaxf(m1.x, m1.y), fmaxf(m1.z, m1.w));
        rsum[mt][0] = 0.f; rsum[mt][1] = 0.f;
    }
#pragma unroll
    for (int mt = 0; mt < 3; mt++)
#pragma unroll
        for (int j = 0; j < 5; j++)
            if (j < quota) {
                accS[mt][j][0] = __expf(accS[mt][j][0] - gmax[mt][0]);
                accS[mt][j][1] = __expf(accS[mt][j][1] - gmax[mt][0]);
                accS[mt][j][2] = __expf(accS[mt][j][2] - gmax[mt][1]);
                accS[mt][j][3] = __expf(accS[mt][j][3] - gmax[mt][1]);
                rsum[mt][0] += accS[mt][j][0] + accS[mt][j][1];
                rsum[mt][1] += accS[mt][j][2] + accS[mt][j][3];
            }
#pragma unroll
    for (int mt = 0; mt < 3; mt++) {
#pragma unroll
        for (int o = 1; o <= 2; o <<= 1) {
            rsum[mt][0] += __shfl_xor_sync(0xffffffff, rsum[mt][0], o);
            rsum[mt][1] += __shfl_xor_sync(0xffffffff, rsum[mt][1], o);
        }
    }
    float* sm2 = reinterpret_cast<float*>(sm + OFF_SM2);
    if ((l & 3) == 0) {
#pragma unroll
        for (int mt = 0; mt < 3; mt++) {
            sm2[(mt * 16 + (l >> 2)) * 4 + w]     = rsum[mt][0];
            sm2[(mt * 16 + 8 + (l >> 2)) * 4 + w] = rsum[mt][1];
        }
    }
    __syncthreads();

    // ---- normalize, split, store Pext ----
    float inv[3][2];
#pragma unroll
    for (int mt = 0; mt < 3; mt++) {
        float4 s0 = *reinterpret_cast<const float4*>(sm2 + (mt * 16 + (l >> 2)) * 4);
        float4 s1 = *reinterpret_cast<const float4*>(sm2 + (mt * 16 + 8 + (l >> 2)) * 4);
        inv[mt][0] = 1.0f / (s0.x + s0.y + s0.z + s0.w);
        inv[mt][1] = 1.0f / (s1.x + s1.y + s1.z + s1.w);
    }
#pragma unroll
    for (int mt = 0; mt < 3; mt++) {
        const int rr = mt * 16 + (l >> 2);
#pragma unroll
        for (int j = 0; j < 5; j++)
            if (j < quota) {
                const int cb = (nb8 + j) * 8 + (l & 3) * 2;
                unsigned short h0, l0, h1, l1, h2, l2, h3, l3;
                bf_split(accS[mt][j][0] * inv[mt][0], h0, l0);
                bf_split(accS[mt][j][1] * inv[mt][0], h1, l1);
                bf_split(accS[mt][j][2] * inv[mt][1], h2, l2);
                bf_split(accS[mt][j][3] * inv[mt][1], h3, l3);
                char* p0 = sm + OFF_P + rr * PPITCH + 2 * cb;
                char* p1 = sm + OFF_P + (rr + 8) * PPITCH + 2 * cb;
                *reinterpret_cast<uint32_t*>(p0)       = (uint32_t)h0 | ((uint32_t)h1 << 16);
                *reinterpret_cast<uint32_t*>(p0 + 288) = (uint32_t)l0 | ((uint32_t)l1 << 16);
                *reinterpret_cast<uint32_t*>(p1)       = (uint32_t)h2 | ((uint32_t)h3 << 16);
                *reinterpret_cast<uint32_t*>(p1 + 288) = (uint32_t)l2 | ((uint32_t)l3 << 16);
            }
    }
    __syncthreads();

    // ---- PV: O[48 x 32] (3 split passes, k=144 each) ----
    float accO[3][4];
#pragma unroll
    for (int mt = 0; mt < 3; mt++)
#pragma unroll
        for (int e = 0; e < 4; e++) accO[mt][e] = 0.f;

    const uint32_t pBase = sb + OFF_P + (l & 15) * PPITCH + (l >> 4) * 16;
    const uint32_t vBase = sb + OFF_V + (w * 8 + (l & 7)) * VPITCH + ((l >> 3) & 1) * 16;
#pragma unroll
    for (int pass = 0; pass < 3; pass++) {
        const int poff = (pass == 1) ? 288 : 0;
        const int voff = (pass == 2) ? 288 : 0;
#pragma unroll
        for (int ks = 0; ks < 9; ks++) {
            uint32_t afr[3][4];
#pragma unroll
            for (int mt = 0; mt < 3; mt++)
                LDMX4(afr[mt][0], afr[mt][1], afr[mt][2], afr[mt][3],
                      pBase + mt * (16 * PPITCH) + poff + ks * 32);
            uint32_t b0, b1;
            LDMX2(b0, b1, vBase + voff + ks * 32);
#pragma unroll
            for (int mt = 0; mt < 3; mt++)
                MMA16816(accO[mt], afr[mt], b0, b1);
        }
    }

    // ---- write O ext [Oh|Ol] ----
#pragma unroll
    for (int mt = 0; mt < 3; mt++) {
        const int r = qbase + mt * 16 + (l >> 2);
        const int d = w * 8 + (l & 3) * 2;
        unsigned short h0, l0, h1, l1, h2, l2, h3, l3;
        bf_split(accO[mt][0], h0, l0); bf_split(accO[mt][1], h1, l1);
        bf_split(accO[mt][2], h2, l2); bf_split(accO[mt][3], h3, l3);
        __nv_bfloat16* o0 = g_attx + (tokBase + r) * KSTORE + h * HD + d;
        __nv_bfloat16* o1 = g_attx + (tokBase + r + 8) * KSTORE + h * HD + d;
        *reinterpret_cast<uint32_t*>(o0)       = (uint32_t)h0 | ((uint32_t)h1 << 16);
        *reinterpret_cast<uint32_t*>(o0 + 256) = (uint32_t)l0 | ((uint32_t)l1 << 16);
        *reinterpret_cast<uint32_t*>(o1)       = (uint32_t)h2 | ((uint32_t)h3 << 16);
        *reinterpret_cast<uint32_t*>(o1 + 256) = (uint32_t)l2 | ((uint32_t)l3 << 16);
    }
}

// ---------------- launch ------------------------------------------------------
extern "C" void kernel_launch(void* const* d_in, const int* in_sizes, int n_in,
                              void* d_out, int out_size) {
    const float* x      = (const float*)d_in[0];
    const float* qkv_w  = (const float*)d_in[1];
    const float* qkv_b  = (const float*)d_in[2];
    const float* proj_w = (const float*)d_in[3];
    const float* proj_b = (const float*)d_in[4];
    const float* rpb    = (const float*)d_in[5];
    const int*   rel    = (const int*)d_in[6];

    uint32_t* qkvbuf = nullptr;
    __nv_bfloat16 *axp = nullptr, *attxp = nullptr, *bqp = nullptr, *bpp = nullptr;
    float* sbp = nullptr;
    cudaGetSymbolAddress((void**)&qkvbuf, g_qkv);
    cudaGetSymbolAddress((void**)&axp,   g_ax);
    cudaGetSymbolAddress((void**)&attxp, g_attx);
    cudaGetSymbolAddress((void**)&bqp,   g_bq);
    cudaGetSymbolAddress((void**)&bpp,   g_bp);
    cudaGetSymbolAddress((void**)&sbp,   g_sbias);

    static bool attr_done = false;
    if (!attr_done) {
        cudaFuncSetAttribute(attn_tc_kernel,
                             cudaFuncAttributeMaxDynamicSharedMemorySize, SMEM_ATTN);
        cudaFuncSetAttribute(gemm_mma_kernel<true>,
                             cudaFuncAttributeMaxDynamicSharedMemorySize, SMEM_GEMM);
        cudaFuncSetAttribute(gemm_mma_kernel<false>,
                             cudaFuncAttributeMaxDynamicSharedMemorySize, SMEM_GEMM);
        attr_done = true;
    }

    // conversions + bias tables (independent)
    conv_x_kernel<<<(NTOK * 64) / 256, 256>>>(x);
    conv_w_kernel<<<(QKVN * 256 + 255) / 256, 256>>>(qkv_w, bqp, QKVN, DIM);
    conv_w_kernel<<<(DIM * 256 + 255) / 256, 256>>>(proj_w, bpp, DIM, 0);
    prep_bias_kernel<<<(QKVN + 255) / 256, 256>>>(qkv_b);
    build_bias_kernel<<<(NW * NW + 255) / 256, 256>>>(rpb, rel);

    // QKV GEMM -> packed (hi|lo) bf16
    gemm_mma_kernel<true><<<dim3(QKVN / 128, NTOK / 128), 256, SMEM_GEMM>>>(
        axp, bqp, sbp, qkvbuf, QKVN);

    // tensor-core attention
    attn_tc_kernel<<<dim3(NH, BnW, 3), 128, SMEM_ATTN>>>();

    // proj GEMM -> fp32 out
    gemm_mma_kernel<false><<<dim3(DIM / 128, NTOK / 128), 256, SMEM_GEMM>>>(
        attxp, bpp, proj_b, d_out, DIM);
}

// round 6
// speedup vs baseline: 2.6680x; 1.1560x over previous
#include <cuda_runtime.h>
#include <cuda_bf16.h>
#include <cstdint>
#include <cstddef>

#define BnW   2048
#define NW    144
#define DIM   256
#define NH    8
#define HD    32
#define NTOK  (BnW * NW)            /* 294912 */
#define QKVN  (3 * DIM)             /* 768 */
#define KSTORE 512                  /* split-bf16 stored K: [hi|lo] */
#define NCHUNK 24                   /* effective K' = 768 in 32-elem chunks */
#define SCALE 0.17677669529663687f

// ---------------- scratch (device globals: allocation-free rule) -------------
__device__ uint32_t      g_qkv[(size_t)NTOK * QKVN];     // packed (hi|lo) bf16 q|k|v
__device__ __nv_bfloat16 g_ax[(size_t)NTOK * KSTORE];    // x ext [Ah|Al]
__device__ __nv_bfloat16 g_attx[(size_t)NTOK * KSTORE];  // attn out ext [Oh|Ol]
__device__ __nv_bfloat16 g_bq[(size_t)QKVN * KSTORE];    // qkv_w ext [Bh|Bl] (q-cols scaled)
__device__ __nv_bfloat16 g_bp[(size_t)DIM * KSTORE];     // proj_w ext
__device__ float         g_sbias[QKVN];                  // scaled qkv bias
__device__ float         g_bias[NH * NW * NW];           // [h][n][m] RPB

// ======================= baseline-PTX tensor-core helpers ====================
__device__ __forceinline__ uint32_t smem_u32(const void* p) {
    uint32_t a;
    asm("{ .reg .u64 t; cvta.to.shared.u64 t, %1; cvt.u32.u64 %0, t; }"
        : "=r"(a) : "l"(p));
    return a;
}
#define LDMX4(r0, r1, r2, r3, addr) \
    asm volatile("ldmatrix.sync.aligned.m8n8.x4.shared.b16 {%0,%1,%2,%3}, [%4];" \
                 : "=r"(r0), "=r"(r1), "=r"(r2), "=r"(r3) : "r"(addr))
#define LDMX2(r0, r1, addr) \
    asm volatile("ldmatrix.sync.aligned.m8n8.x2.shared.b16 {%0,%1}, [%2];" \
                 : "=r"(r0), "=r"(r1) : "r"(addr))
#define MMA16816(d, a, b0, b1) \
    asm volatile("mma.sync.aligned.m16n8k16.row.col.f32.bf16.bf16.f32 " \
                 "{%0,%1,%2,%3}, {%4,%5,%6,%7}, {%8,%9}, {%0,%1,%2,%3};" \
                 : "+f"((d)[0]), "+f"((d)[1]), "+f"((d)[2]), "+f"((d)[3]) \
                 : "r"((a)[0]), "r"((a)[1]), "r"((a)[2]), "r"((a)[3]), \
                   "r"(b0), "r"(b1))
#define CPASYNC16(s, g) \
    asm volatile("cp.async.cg.shared.global [%0], [%1], 16;" :: "r"(s), "l"(g))
#define CP_COMMIT() asm volatile("cp.async.commit_group;" ::: "memory")
#define CP_WAIT1()  asm volatile("cp.async.wait_group 1;" ::: "memory")
#define CP_WAIT0()  asm volatile("cp.async.wait_group 0;" ::: "memory")

// ======================= split-bf16 helpers ==================================
__device__ __forceinline__ void bf_split(float f, unsigned short& h, unsigned short& l) {
    __nv_bfloat16 hb = __float2bfloat16(f);
    __nv_bfloat16 lb = __float2bfloat16(f - __bfloat162float(hb));
    h = __bfloat16_as_ushort(hb);
    l = __bfloat16_as_ushort(lb);
}
__device__ __forceinline__ uint32_t pack_hl(float f) {
    unsigned short h, l;
    bf_split(f, h, l);
    return (uint32_t)h | ((uint32_t)l << 16);
}
// split two floats -> (hi-pair, lo-pair) packed bf16x2
__device__ __forceinline__ void split2(float x, float y, uint32_t& hp, uint32_t& lp) {
    unsigned short hx, lx, hy, ly;
    bf_split(x, hx, lx);
    bf_split(y, hy, ly);
    hp = (uint32_t)hx | ((uint32_t)hy << 16);
    lp = (uint32_t)lx | ((uint32_t)ly << 16);
}

// x [NTOK,256] fp32 -> g_ax [NTOK,512] = [Ah|Al]
__global__ __launch_bounds__(256) void conv_x_kernel(const float* __restrict__ x) {
    size_t i = (size_t)blockIdx.x * 256 + threadIdx.x;   // over NTOK*64
    size_t row = i >> 6;
    int c4 = (int)(i & 63) * 4;
    float4 v = *reinterpret_cast<const float4*>(x + row * DIM + c4);
    ushort4 hv, lv;
    bf_split(v.x, hv.x, lv.x); bf_split(v.y, hv.y, lv.y);
    bf_split(v.z, hv.z, lv.z); bf_split(v.w, hv.w, lv.w);
    __nv_bfloat16* base = g_ax + row * KSTORE;
    *reinterpret_cast<ushort4*>(base + c4)       = hv;
    *reinterpret_cast<ushort4*>(base + 256 + c4) = lv;
}

// w [256,N] fp32 -> Bext [N,512] = [Bh|Bl]; first nscale output cols scaled
__global__ __launch_bounds__(256) void conv_w_kernel(const float* __restrict__ w,
                                                     __nv_bfloat16* __restrict__ Bext,
                                                     int N, int nscale) {
    int i = blockIdx.x * 256 + threadIdx.x;   // over N*256
    if (i >= N * 256) return;
    int n = i >> 8, k = i & 255;
    float val = w[k * N + n];
    if (n < nscale) val *= SCALE;
    unsigned short h, l;
    bf_split(val, h, l);
    Bext[(size_t)n * KSTORE + k]       = __ushort_as_bfloat16(h);
    Bext[(size_t)n * KSTORE + 256 + k] = __ushort_as_bfloat16(l);
}

__global__ void prep_bias_kernel(const float* __restrict__ qkv_b) {
    int i = blockIdx.x * 256 + threadIdx.x;
    if (i < QKVN) g_sbias[i] = qkv_b[i] * (i < DIM ? SCALE : 1.0f);
}

// bias[h][n][m] = rpb[rel[n][m]][h]
__global__ __launch_bounds__(256) void build_bias_kernel(
    const float* __restrict__ rpb, const int* __restrict__ rel) {
    int idx = blockIdx.x * 256 + threadIdx.x;
    if (idx < NW * NW) {
        int r = rel[idx];
#pragma unroll
        for (int h = 0; h < NH; h++)
            g_bias[h * (NW * NW) + idx] = rpb[r * NH + h];
    }
}

// ======================= mma.sync GEMM: C = Aext @ Bext^T + bias =============
#define SPITCH 80
#define STAGE_BYTES (128 * SPITCH)
#define SMEM_GEMM (6 * STAGE_BYTES)       /* 61440 */

template <bool PACK>
__global__ __launch_bounds__(256, 2) void gemm_mma_kernel(
    const __nv_bfloat16* __restrict__ Aext,
    const __nv_bfloat16* __restrict__ Bext,
    const float* __restrict__ bias,
    void* __restrict__ Cout, int Ntot) {
    extern __shared__ char gsm[];
    const uint32_t sAb = smem_u32(gsm);
    const uint32_t sBb = sAb + 3 * STAGE_BYTES;

    const int tid = threadIdx.x;
    const int w = tid >> 5, l = tid & 31;
    const int wm = w & 1, wn = w >> 1;
    const int tileN = blockIdx.x, tileM = blockIdx.y;

    const char* Ab = reinterpret_cast<const char*>(Aext) +
                     (size_t)tileM * 128 * (KSTORE * 2);
    const char* Bb = reinterpret_cast<const char*>(Bext) +
                     (size_t)tileN * 128 * (KSTORE * 2);

    const int lrow = tid >> 2;
    const int lseg = (tid & 3) * 16;

    float acc[4][4][4];
#pragma unroll
    for (int mf = 0; mf < 4; mf++)
#pragma unroll
        for (int nf = 0; nf < 4; nf++)
#pragma unroll
            for (int r = 0; r < 4; r++) acc[mf][nf][r] = 0.f;

#define ISSUE_CHUNK(cc) do {                                                      \
        const int _c = (cc);                                                      \
        const int _aoff = (_c < 16) ? _c : _c - 16;                               \
        const int _boff = (_c < 8) ? _c : _c - 8;                                 \
        const int _buf = _c % 3;                                                  \
        const size_t _gaA = (size_t)lrow * (KSTORE * 2) + _aoff * 64 + lseg;      \
        const size_t _gaA2 = (size_t)(lrow + 64) * (KSTORE * 2) + _aoff * 64 + lseg; \
        const size_t _gaB = (size_t)lrow * (KSTORE * 2) + _boff * 64 + lseg;      \
        const size_t _gaB2 = (size_t)(lrow + 64) * (KSTORE * 2) + _boff * 64 + lseg; \
        CPASYNC16(sAb + _buf * STAGE_BYTES + lrow * SPITCH + lseg, Ab + _gaA);    \
        CPASYNC16(sAb + _buf * STAGE_BYTES + (lrow + 64) * SPITCH + lseg, Ab + _gaA2); \
        CPASYNC16(sBb + _buf * STAGE_BYTES + lrow * SPITCH + lseg, Bb + _gaB);    \
        CPASYNC16(sBb + _buf * STAGE_BYTES + (lrow + 64) * SPITCH + lseg, Bb + _gaB2); \
        CP_COMMIT();                                                              \
    } while (0)

    ISSUE_CHUNK(0);
    ISSUE_CHUNK(1);

    const uint32_t aRowOff = (uint32_t)(wm * 64 + (l & 15)) * SPITCH + (l >> 4) * 16;
    const uint32_t bRowOff = (uint32_t)(wn * 32 + ((l >> 4) * 8 + (l & 7))) * SPITCH +
                             ((l >> 3) & 1) * 16;

    for (int c = 0; c < NCHUNK; c++) {
        if (c < NCHUNK - 1) CP_WAIT1(); else CP_WAIT0();
        __syncthreads();
        if (c + 2 < NCHUNK) ISSUE_CHUNK(c + 2);

        const uint32_t stg = (uint32_t)(c % 3) * STAGE_BYTES;
        const uint32_t aS = sAb + stg + aRowOff;
        const uint32_t bS = sBb + stg + bRowOff;
#pragma unroll
        for (int ks = 0; ks < 2; ks++) {
            uint32_t afr[4][4], bfr[2][4];
#pragma unroll
            for (int mf = 0; mf < 4; mf++)
                LDMX4(afr[mf][0], afr[mf][1], afr[mf][2], afr[mf][3],
                      aS + mf * (16 * SPITCH) + ks * 32);
#pragma unroll
            for (int n2 = 0; n2 < 2; n2++)
                LDMX4(bfr[n2][0], bfr[n2][1], bfr[n2][2], bfr[n2][3],
                      bS + n2 * (16 * SPITCH) + ks * 32);
#pragma unroll
            for (int mf = 0; mf < 4; mf++)
#pragma unroll
                for (int nf = 0; nf < 4; nf++)
                    MMA16816(acc[mf][nf], afr[mf],
                             bfr[nf >> 1][(nf & 1) * 2],
                             bfr[nf >> 1][(nf & 1) * 2 + 1]);
        }
    }
#undef ISSUE_CHUNK

    const int rbase = tileM * 128 + wm * 64 + (l >> 2);
    const int cbase = tileN * 128 + wn * 32 + (l & 3) * 2;
#pragma unroll
    for (int mf = 0; mf < 4; mf++) {
#pragma unroll
        for (int nf = 0; nf < 4; nf++) {
            const int col = cbase + nf * 8;
            const float b0 = bias[col], b1 = bias[col + 1];
            const size_t r0 = (size_t)(rbase + mf * 16) * Ntot + col;
            const size_t r1 = r0 + (size_t)8 * Ntot;
            if (PACK) {
                uint32_t* C = reinterpret_cast<uint32_t*>(Cout);
                *reinterpret_cast<uint2*>(C + r0) =
                    make_uint2(pack_hl(acc[mf][nf][0] + b0), pack_hl(acc[mf][nf][1] + b1));
                *reinterpret_cast<uint2*>(C + r1) =
                    make_uint2(pack_hl(acc[mf][nf][2] + b0), pack_hl(acc[mf][nf][3] + b1));
            } else {
                float* C = reinterpret_cast<float*>(Cout);
                *reinterpret_cast<float2*>(C + r0) =
                    make_float2(acc[mf][nf][0] + b0, acc[mf][nf][1] + b1);
                *reinterpret_cast<float2*>(C + r1) =
                    make_float2(acc[mf][nf][2] + b0, acc[mf][nf][3] + b1);
            }
        }
    }
}

// ======================= tensor-core attention v2 ============================
// one block per (head, window): 288 threads = 9 warps, warp grid 3M x 3N.
// K/V staged ONCE; P stays in registers (accumulator frag == A frag).
#define QPITCH 144                        /* [Qh 64B | Ql 64B | pad] */
#define KPITCH 144
#define VPITCH 592                        /* [Vh 288 | Vl 288 | pad] */
#define OPITCH 36                         /* floats */
#define OFF_Q   0
#define OFF_K   (144 * QPITCH)            /* 20736 */
#define OFF_V   (OFF_K + 144 * KPITCH)    /* 41472 */
#define OFF_O   (OFF_V + 32 * VPITCH)     /* 60416 */
#define OFF_MX  (OFF_O + 144 * OPITCH * 4)/* 81152 */
#define OFF_SM2 (OFF_MX + 144 * 3 * 4)    /* 82880 */
#define SMEM_ATTN (OFF_SM2 + 144 * 3 * 4) /* 84608 */

__global__ __launch_bounds__(288, 1) void attn_tc_kernel() {
    extern __shared__ char sm[];
    const uint32_t sb = smem_u32(sm);
    const int tid = threadIdx.x, l = tid & 31, w = tid >> 5;
    const int wm = w / 3, wn = w % 3;          // 3M x 3N warp grid
    const int h = blockIdx.x, b = blockIdx.y;
    const size_t tokBase = (size_t)b * NW;
    float* O = reinterpret_cast<float*>(sm + OFF_O);

    // ---- zero O accumulator ----
    for (int idx = tid; idx < 144 * OPITCH / 2; idx += 288)
        *reinterpret_cast<float2*>(O + idx * 2) = make_float2(0.f, 0.f);

    // ---- stage Q and K (packed (hi|lo) -> [hi row | lo row]) ----
    for (int idx = tid; idx < 144 * 8; idx += 288) {
        int r = idx >> 3, d4 = (idx & 7) * 4;
        uint4 q = *reinterpret_cast<const uint4*>(
            g_qkv + (tokBase + r) * QKVN + h * HD + d4);
        char* qb = sm + OFF_Q + r * QPITCH + d4 * 2;
        *reinterpret_cast<uint32_t*>(qb)      = __byte_perm(q.x, q.y, 0x5410);
        *reinterpret_cast<uint32_t*>(qb + 4)  = __byte_perm(q.z, q.w, 0x5410);
        *reinterpret_cast<uint32_t*>(qb + 64) = __byte_perm(q.x, q.y, 0x7632);
        *reinterpret_cast<uint32_t*>(qb + 68) = __byte_perm(q.z, q.w, 0x7632);
        uint4 k = *reinterpret_cast<const uint4*>(
            g_qkv + (tokBase + r) * QKVN + DIM + h * HD + d4);
        char* kb = sm + OFF_K + r * KPITCH + d4 * 2;
        *reinterpret_cast<uint32_t*>(kb)      = __byte_perm(k.x, k.y, 0x5410);
        *reinterpret_cast<uint32_t*>(kb + 4)  = __byte_perm(k.z, k.w, 0x5410);
        *reinterpret_cast<uint32_t*>(kb + 64) = __byte_perm(k.x, k.y, 0x7632);
        *reinterpret_cast<uint32_t*>(kb + 68) = __byte_perm(k.z, k.w, 0x7632);
    }
    // ---- stage V transposed ----
    for (int idx = tid; idx < 144 * 8; idx += 288) {
        int m = idx >> 3, d4 = (idx & 7) * 4;
        uint4 e = *reinterpret_cast<const uint4*>(
            g_qkv + (tokBase + m) * QKVN + 2 * DIM + h * HD + d4);
        uint32_t ev[4] = {e.x, e.y, e.z, e.w};
#pragma unroll
        for (int j = 0; j < 4; j++) {
            char* base = sm + OFF_V + (d4 + j) * VPITCH + 2 * m;
            *reinterpret_cast<unsigned short*>(base)       = (unsigned short)ev[j];
            *reinterpret_cast<unsigned short*>(base + 288) = (unsigned short)(ev[j] >> 16);
        }
    }
    __syncthreads();

    // ---- QK^T: warp computes S[wm*48..+47][wn*48..+47] (3 split passes) ----
    float accS[3][6][4];
#pragma unroll
    for (int mt = 0; mt < 3; mt++)
#pragma unroll
        for (int j = 0; j < 6; j++)
#pragma unroll
            for (int e = 0; e < 4; e++) accS[mt][j][e] = 0.f;

    const uint32_t aBase = sb + OFF_Q + (wm * 48 + (l & 15)) * QPITCH + (l >> 4) * 16;
    const uint32_t bBase = sb + OFF_K +
        (wn * 48 + ((l >> 4) & 1) * 8 + (l & 7)) * KPITCH + ((l >> 3) & 1) * 16;
#pragma unroll
    for (int pass = 0; pass < 3; pass++) {
        const int aoff = (pass == 1) ? 64 : 0;
        const int boff = (pass == 2) ? 64 : 0;
#pragma unroll
        for (int ks = 0; ks < 2; ks++) {
            uint32_t afr[3][4], bfr[3][4];
#pragma unroll
            for (int mt = 0; mt < 3; mt++)
                LDMX4(afr[mt][0], afr[mt][1], afr[mt][2], afr[mt][3],
                      aBase + mt * (16 * QPITCH) + aoff + ks * 32);
#pragma unroll
            for (int jp = 0; jp < 3; jp++)
                LDMX4(bfr[jp][0], bfr[jp][1], bfr[jp][2], bfr[jp][3],
                      bBase + jp * (16 * KPITCH) + boff + ks * 32);
#pragma unroll
            for (int mt = 0; mt < 3; mt++)
#pragma unroll
                for (int j = 0; j < 6; j++)
                    MMA16816(accS[mt][j], afr[mt],
                             bfr[j >> 1][(j & 1) * 2],
                             bfr[j >> 1][(j & 1) * 2 + 1]);
        }
    }

    // ---- bias add + warp-partial row max ----
    const float* bh = g_bias + h * (NW * NW);
    float rmax[3][2];
#pragma unroll
    for (int mt = 0; mt < 3; mt++) { rmax[mt][0] = -1e30f; rmax[mt][1] = -1e30f; }
#pragma unroll
    for (int mt = 0; mt < 3; mt++) {
        const int r = wm * 48 + mt * 16 + (l >> 2);
#pragma unroll
        for (int j = 0; j < 6; j++) {
            const int c = wn * 48 + j * 8 + (l & 3) * 2;
            float2 b0 = *reinterpret_cast<const float2*>(bh + r * NW + c);
            float2 b1 = *reinterpret_cast<const float2*>(bh + (r + 8) * NW + c);
            accS[mt][j][0] += b0.x; accS[mt][j][1] += b0.y;
            accS[mt][j][2] += b1.x; accS[mt][j][3] += b1.y;
            rmax[mt][0] = fmaxf(rmax[mt][0], fmaxf(accS[mt][j][0], accS[mt][j][1]));
            rmax[mt][1] = fmaxf(rmax[mt][1], fmaxf(accS[mt][j][2], accS[mt][j][3]));
        }
    }
#pragma unroll
    for (int mt = 0; mt < 3; mt++) {
#pragma unroll
        for (int o = 1; o <= 2; o <<= 1) {
            rmax[mt][0] = fmaxf(rmax[mt][0], __shfl_xor_sync(0xffffffff, rmax[mt][0], o));
            rmax[mt][1] = fmaxf(rmax[mt][1], __shfl_xor_sync(0xffffffff, rmax[mt][1], o));
        }
    }
    float* mx = reinterpret_cast<float*>(sm + OFF_MX);
    if ((l & 3) == 0) {
#pragma unroll
        for (int mt = 0; mt < 3; mt++) {
            mx[(wm * 48 + mt * 16 + (l >> 2)) * 3 + wn]     = rmax[mt][0];
            mx[(wm * 48 + mt * 16 + 8 + (l >> 2)) * 3 + wn] = rmax[mt][1];
        }
    }
    __syncthreads();

    // ---- exp + warp-partial row sum ----
    float gmax[3][2], rsum[3][2];
#pragma unroll
    for (int mt = 0; mt < 3; mt++) {
        const int r0 = (wm * 48 + mt * 16 + (l >> 2)) * 3;
        const int r1 = (wm * 48 + mt * 16 + 8 + (l >> 2)) * 3;
        gmax[mt][0] = fmaxf(fmaxf(mx[r0], mx[r0 + 1]), mx[r0 + 2]);
        gmax[mt][1] = fmaxf(fmaxf(mx[r1], mx[r1 + 1]), mx[r1 + 2]);
        rsum[mt][0] = 0.f; rsum[mt][1] = 0.f;
    }
#pragma unroll
    for (int mt = 0; mt < 3; mt++)
#pragma unroll
        for (int j = 0; j < 6; j++) {
            accS[mt][j][0] = __expf(accS[mt][j][0] - gmax[mt][0]);
            accS[mt][j][1] = __expf(accS[mt][j][1] - gmax[mt][0]);
            accS[mt][j][2] = __expf(accS[mt][j][2] - gmax[mt][1]);
            accS[mt][j][3] = __expf(accS[mt][j][3] - gmax[mt][1]);
            rsum[mt][0] += accS[mt][j][0] + accS[mt][j][1];
            rsum[mt][1] += accS[mt][j][2] + accS[mt][j][3];
        }
#pragma unroll
    for (int mt = 0; mt < 3; mt++) {
#pragma unroll
        for (int o = 1; o <= 2; o <<= 1) {
            rsum[mt][0] += __shfl_xor_sync(0xffffffff, rsum[mt][0], o);
            rsum[mt][1] += __shfl_xor_sync(0xffffffff, rsum[mt][1], o);
        }
    }
    float* sm2 = reinterpret_cast<float*>(sm + OFF_SM2);
    if ((l & 3) == 0) {
#pragma unroll
        for (int mt = 0; mt < 3; mt++) {
            sm2[(wm * 48 + mt * 16 + (l >> 2)) * 3 + wn]     = rsum[mt][0];
            sm2[(wm * 48 + mt * 16 + 8 + (l >> 2)) * 3 + wn] = rsum[mt][1];
        }
    }
    __syncthreads();

    // ---- normalize + build P A-fragments IN REGISTERS (hi & lo splits) ----
    float inv[3][2];
#pragma unroll
    for (int mt = 0; mt < 3; mt++) {
        const int r0 = (wm * 48 + mt * 16 + (l >> 2)) * 3;
        const int r1 = (wm * 48 + mt * 16 + 8 + (l >> 2)) * 3;
        inv[mt][0] = 1.0f / (sm2[r0] + sm2[r0 + 1] + sm2[r0 + 2]);
        inv[mt][1] = 1.0f / (sm2[r1] + sm2[r1 + 1] + sm2[r1 + 2]);
    }
    uint32_t ph[3][3][4], pl[3][3][4];
#pragma unroll
    for (int mt = 0; mt < 3; mt++)
#pragma unroll
        for (int kk = 0; kk < 3; kk++) {
            const int j0 = 2 * kk, j1 = 2 * kk + 1;
            split2(accS[mt][j0][0] * inv[mt][0], accS[mt][j0][1] * inv[mt][0],
                   ph[mt][kk][0], pl[mt][kk][0]);
            split2(accS[mt][j0][2] * inv[mt][1], accS[mt][j0][3] * inv[mt][1],
                   ph[mt][kk][1], pl[mt][kk][1]);
            split2(accS[mt][j1][0] * inv[mt][0], accS[mt][j1][1] * inv[mt][0],
                   ph[mt][kk][2], pl[mt][kk][2]);
            split2(accS[mt][j1][2] * inv[mt][1], accS[mt][j1][3] * inv[mt][1],
                   ph[mt][kk][3], pl[mt][kk][3]);
        }

    // ---- PV: partial O[wm rows][32] over this warp's 48-key slice ----
    float accO[3][4][4];
#pragma unroll
    for (int mt = 0; mt < 3; mt++)
#pragma unroll
        for (int j = 0; j < 4; j++)
#pragma unroll
            for (int e = 0; e < 4; e++) accO[mt][j][e] = 0.f;

    const uint32_t vBase = sb + OFF_V +
        (((l >> 4) & 1) * 8 + (l & 7)) * VPITCH + ((l >> 3) & 1) * 16 +
        2 * (wn * 48);
#pragma unroll
    for (int kk = 0; kk < 3; kk++) {
        uint32_t vh[2][4], vl[2][4];
#pragma unroll
        for (int jp = 0; jp < 2; jp++)
            LDMX4(vh[jp][0], vh[jp][1], vh[jp][2], vh[jp][3],
                  vBase + jp * (16 * VPITCH) + kk * 32);
#pragma unroll
        for (int mt = 0; mt < 3; mt++)
#pragma unroll
            for (int j = 0; j < 4; j++) {
                MMA16816(accO[mt][j], ph[mt][kk],
                         vh[j >> 1][(j & 1) * 2], vh[j >> 1][(j & 1) * 2 + 1]);
                MMA16816(accO[mt][j], pl[mt][kk],
                         vh[j >> 1][(j & 1) * 2], vh[j >> 1][(j & 1) * 2 + 1]);
            }
#pragma unroll
        for (int jp = 0; jp < 2; jp++)
            LDMX4(vl[jp][0], vl[jp][1], vl[jp][2], vl[jp][3],
                  vBase + jp * (16 * VPITCH) + kk * 32 + 288);
#pragma unroll
        for (int mt = 0; mt < 3; mt++)
#pragma unroll
            for (int j = 0; j < 4; j++)
                MMA16816(accO[mt][j], ph[mt][kk],
                         vl[j >> 1][(j & 1) * 2], vl[j >> 1][(j & 1) * 2 + 1]);
    }

    // ---- cross-warp (over wn) reduction into O smem ----
#pragma unroll
    for (int mt = 0; mt < 3; mt++) {
        const int r = wm * 48 + mt * 16 + (l >> 2);
#pragma unroll
        for (int j = 0; j < 4; j++) {
            const int cc = j * 8 + (l & 3) * 2;
            atomicAdd(&O[r * OPITCH + cc],           accO[mt][j][0]);
            atomicAdd(&O[r * OPITCH + cc + 1],       accO[mt][j][1]);
            atomicAdd(&O[(r + 8) * OPITCH + cc],     accO[mt][j][2]);
            atomicAdd(&O[(r + 8) * OPITCH + cc + 1], accO[mt][j][3]);
        }
    }
    __syncthreads();

    // ---- split + write O ext [Oh|Ol] ----
    for (int idx = tid; idx < 144 * 16; idx += 288) {
        const int r = idx >> 4, d = (idx & 15) * 2;
        uint32_t hp, lp;
        split2(O[r * OPITCH + d], O[r * OPITCH + d + 1], hp, lp);
        __nv_bfloat16* o = g_attx + (tokBase + r) * KSTORE + h * HD + d;
        *reinterpret_cast<uint32_t*>(o)       = hp;
        *reinterpret_cast<uint32_t*>(o + 256) = lp;
    }
}

// ---------------- launch ------------------------------------------------------
extern "C" void kernel_launch(void* const* d_in, const int* in_sizes, int n_in,
                              void* d_out, int out_size) {
    const float* x      = (const float*)d_in[0];
    const float* qkv_w  = (const float*)d_in[1];
    const float* qkv_b  = (const float*)d_in[2];
    const float* proj_w = (const float*)d_in[3];
    const float* proj_b = (const float*)d_in[4];
    const float* rpb    = (const float*)d_in[5];
    const int*   rel    = (const int*)d_in[6];

    uint32_t* qkvbuf = nullptr;
    __nv_bfloat16 *axp = nullptr, *attxp = nullptr, *bqp = nullptr, *bpp = nullptr;
    float* sbp = nullptr;
    cudaGetSymbolAddress((void**)&qkvbuf, g_qkv);
    cudaGetSymbolAddress((void**)&axp,   g_ax);
    cudaGetSymbolAddress((void**)&attxp, g_attx);
    cudaGetSymbolAddress((void**)&bqp,   g_bq);
    cudaGetSymbolAddress((void**)&bpp,   g_bp);
    cudaGetSymbolAddress((void**)&sbp,   g_sbias);

    static bool attr_done = false;
    if (!attr_done) {
        cudaFuncSetAttribute(attn_tc_kernel,
                             cudaFuncAttributeMaxDynamicSharedMemorySize, SMEM_ATTN);
        cudaFuncSetAttribute(gemm_mma_kernel<true>,
                             cudaFuncAttributeMaxDynamicSharedMemorySize, SMEM_GEMM);
        cudaFuncSetAttribute(gemm_mma_kernel<false>,
                             cudaFuncAttributeMaxDynamicSharedMemorySize, SMEM_GEMM);
        attr_done = true;
    }

    // conversions + bias tables (independent)
    conv_x_kernel<<<(NTOK * 64) / 256, 256>>>(x);
    conv_w_kernel<<<(QKVN * 256 + 255) / 256, 256>>>(qkv_w, bqp, QKVN, DIM);
    conv_w_kernel<<<(DIM * 256 + 255) / 256, 256>>>(proj_w, bpp, DIM, 0);
    prep_bias_kernel<<<(QKVN + 255) / 256, 256>>>(qkv_b);
    build_bias_kernel<<<(NW * NW + 255) / 256, 256>>>(rpb, rel);

    // QKV GEMM -> packed (hi|lo) bf16
    gemm_mma_kernel<true><<<dim3(QKVN / 128, NTOK / 128), 256, SMEM_GEMM>>>(
        axp, bqp, sbp, qkvbuf, QKVN);

    // tensor-core attention (one block per head x window)
    attn_tc_kernel<<<dim3(NH, BnW), 288, SMEM_ATTN>>>();

    // proj GEMM -> fp32 out
    gemm_mma_kernel<false><<<dim3(DIM / 128, NTOK / 128), 256, SMEM_GEMM>>>(
        attxp, bpp, proj_b, d_out, DIM);
}